// round 2
// baseline (speedup 1.0000x reference)
#include <cuda_runtime.h>
#include <cuda_bf16.h>
#include <cstdint>
#include <cstddef>

#define NN 100000
#define HH 128
#define EE 1600000
#define EPP 200000

// ---------------- scratch (device globals; no allocation allowed) ----------------
__device__ float g_xw[(size_t)NN * HH];
__device__ float g_h1[(size_t)NN * HH];
__device__ float g_h2[(size_t)NN * HH];
__device__ float g_dinv[NN];
__device__ float g_cnorm[EE];
__device__ int   g_cnt[NN];
__device__ int   g_fill[NN];
__device__ int   g_rowptr[NN + 1];
__device__ int   g_bsums[256];
__device__ int   g_csrc[EE];
__device__ int   g_pcnt[NN];
__device__ int   g_pfill[NN];
__device__ int   g_prow[NN + 1];
__device__ int   g_pnode[NN];
__device__ int   g_is64[1];

// ---------------- index dtype detection + accessor ----------------
// int64 data with values < 2^31 has zero high words everywhere; int32 data's
// "high words" are the next random indices (virtually never all zero).
__global__ void detect_kernel(const void* __restrict__ p, int* __restrict__ flag) {
    const int2* q = (const int2*)p;
    __shared__ int any_hi;
    if (threadIdx.x == 0) any_hi = 0;
    __syncthreads();
    for (int i = threadIdx.x; i < 1024; i += blockDim.x)
        if (q[i].y != 0) any_hi = 1;
    __syncthreads();
    if (threadIdx.x == 0) flag[0] = any_hi ? 0 : 1;   // 1 => int64
}

__device__ __forceinline__ int idx_at(const void* __restrict__ p, long long i, int is64) {
    if (is64) return (int)((const long long*)p)[i];
    return ((const int*)p)[i];
}

// ---------------- small utility kernels ----------------
__global__ void zero_counts_kernel(int* cnt, int* fill, int* pcnt, int* pfill, int n) {
    int i = blockIdx.x * blockDim.x + threadIdx.x;
    if (i < n) { cnt[i] = 0; fill[i] = 0; pcnt[i] = 0; pfill[i] = 0; }
}

__global__ void hist_kernel(const void* __restrict__ idx, long long base,
                            const int* __restrict__ flag, int* __restrict__ cnt, int n) {
    int is64 = flag[0];
    int i = blockIdx.x * blockDim.x + threadIdx.x;
    int stride = gridDim.x * blockDim.x;
    for (; i < n; i += stride) atomicAdd(&cnt[idx_at(idx, base + i, is64)], 1);
}

__global__ void dinv_kernel(const int* __restrict__ cnt, float* __restrict__ dinv, int n) {
    int i = blockIdx.x * blockDim.x + threadIdx.x;
    if (i < n) dinv[i] = rsqrtf((float)(cnt[i] + 1));   // +1 self-loop; always > 0
}

// ---------------- exclusive scan (3-phase, 1024 elems/block) ----------------
__global__ void scan1_kernel(const int* __restrict__ cnt, int* __restrict__ rp,
                             int* __restrict__ bs, int n) {
    __shared__ int sh[1024];
    int tid = threadIdx.x;
    int i = blockIdx.x * 1024 + tid;
    int v = (i < n) ? cnt[i] : 0;
    sh[tid] = v;
    __syncthreads();
    #pragma unroll
    for (int off = 1; off < 1024; off <<= 1) {
        int t = (tid >= off) ? sh[tid - off] : 0;
        __syncthreads();
        sh[tid] += t;
        __syncthreads();
    }
    if (i < n) rp[i] = sh[tid] - v;           // exclusive
    if (tid == 1023) bs[blockIdx.x] = sh[1023];
}

__global__ void scan2_kernel(int* bs, int nb, int* rp, int n) {
    if (threadIdx.x == 0 && blockIdx.x == 0) {
        int run = 0;
        for (int b = 0; b < nb; b++) { int t = bs[b]; bs[b] = run; run += t; }
        rp[n] = run;
    }
}

__global__ void scan3_kernel(int* rp, const int* __restrict__ bs, int n) {
    int i = blockIdx.x * blockDim.x + threadIdx.x;
    if (i < n) rp[i] += bs[i >> 10];
}

// ---------------- CSR scatter ----------------
__global__ void scatter_edges_kernel(const void* __restrict__ edge, long long ne,
                                     const int* __restrict__ flag,
                                     const int* __restrict__ rowptr, int* __restrict__ fill,
                                     int* __restrict__ csrc, float* __restrict__ cnorm,
                                     const float* __restrict__ dinv, int n) {
    int is64 = flag[0];
    int e = blockIdx.x * blockDim.x + threadIdx.x;
    int stride = gridDim.x * blockDim.x;
    for (; e < n; e += stride) {
        int s = idx_at(edge, e, is64);
        int d = idx_at(edge, ne + e, is64);
        int p = rowptr[d] + atomicAdd(&fill[d], 1);
        csrc[p] = s;
        cnorm[p] = dinv[s] * dinv[d];
    }
}

__global__ void scatter_pool_kernel(const void* __restrict__ dict,
                                    const int* __restrict__ flag,
                                    const int* __restrict__ prow, int* __restrict__ pfill,
                                    int* __restrict__ pnode, int n) {
    int is64 = flag[0];
    int v = blockIdx.x * blockDim.x + threadIdx.x;
    if (v < n) {
        int d = idx_at(dict, v, is64);
        int p = prow[d] + atomicAdd(&pfill[d], 1);
        pnode[p] = v;
    }
}

// ---------------- fp32 GEMM: C[n,128] = A[n,128] @ W[128,128] ----------------
#define BM 64
#define BK 16
__global__ void gemm128_kernel(const float* __restrict__ A, const float* __restrict__ W,
                               float* __restrict__ C, int n) {
    __shared__ __align__(16) float As[BM][BK + 1];
    __shared__ __align__(16) float Ws[BK][128];
    int tid = threadIdx.x;
    int row0 = blockIdx.x * BM;
    int tr = tid >> 4;         // 0..15 (row group of 4)
    int tc = tid & 15;         // 0..15 (col group of 8)
    int ar = tid >> 2;         // 0..63
    int ak4 = (tid & 3) * 4;   // 0,4,8,12

    float acc[4][8];
    #pragma unroll
    for (int i = 0; i < 4; i++)
        #pragma unroll
        for (int j = 0; j < 8; j++) acc[i][j] = 0.f;

    for (int kt = 0; kt < 128; kt += BK) {
        // A tile 64x16
        float4 av = make_float4(0.f, 0.f, 0.f, 0.f);
        int grow = row0 + ar;
        if (grow < n)
            av = *reinterpret_cast<const float4*>(A + (size_t)grow * 128 + kt + ak4);
        As[ar][ak4 + 0] = av.x; As[ar][ak4 + 1] = av.y;
        As[ar][ak4 + 2] = av.z; As[ar][ak4 + 3] = av.w;
        // W tile 16x128 (contiguous rows kt..kt+15)
        const float4* Wv = reinterpret_cast<const float4*>(W + (size_t)kt * 128);
        float4* Wsv = reinterpret_cast<float4*>(&Ws[0][0]);
        Wsv[tid] = Wv[tid];
        Wsv[tid + 256] = Wv[tid + 256];
        __syncthreads();
        #pragma unroll
        for (int k = 0; k < BK; k++) {
            float a[4];
            #pragma unroll
            for (int i = 0; i < 4; i++) a[i] = As[tr * 4 + i][k];
            float w[8];
            *reinterpret_cast<float4*>(&w[0]) = *reinterpret_cast<const float4*>(&Ws[k][tc * 8]);
            *reinterpret_cast<float4*>(&w[4]) = *reinterpret_cast<const float4*>(&Ws[k][tc * 8 + 4]);
            #pragma unroll
            for (int i = 0; i < 4; i++)
                #pragma unroll
                for (int j = 0; j < 8; j++) acc[i][j] += a[i] * w[j];
        }
        __syncthreads();
    }
    #pragma unroll
    for (int i = 0; i < 4; i++) {
        int grow = row0 + tr * 4 + i;
        if (grow < n) {
            float4 o0 = make_float4(acc[i][0], acc[i][1], acc[i][2], acc[i][3]);
            float4 o1 = make_float4(acc[i][4], acc[i][5], acc[i][6], acc[i][7]);
            *reinterpret_cast<float4*>(C + (size_t)grow * 128 + tc * 8) = o0;
            *reinterpret_cast<float4*>(C + (size_t)grow * 128 + tc * 8 + 4) = o1;
        }
    }
}

// ---------------- GCN aggregation: block per dst node, thread per feature ----------------
__global__ void agg_kernel(const float* __restrict__ xw, float* __restrict__ out,
                           const float* __restrict__ bias,
                           const int* __restrict__ rowptr, const int* __restrict__ csrc,
                           const float* __restrict__ cnorm, const float* __restrict__ dinv) {
    int v = blockIdx.x;
    int f = threadIdx.x;
    int beg = rowptr[v];
    int end = rowptr[v + 1];
    float acc = 0.f;
    int e = beg;
    for (; e + 1 < end; e += 2) {
        int s0 = csrc[e];
        int s1 = csrc[e + 1];
        float n0 = cnorm[e];
        float n1 = cnorm[e + 1];
        float x0 = xw[(size_t)s0 * 128 + f];
        float x1 = xw[(size_t)s1 * 128 + f];
        acc += x0 * n0 + x1 * n1;
    }
    if (e < end) {
        int s = csrc[e];
        acc += xw[(size_t)s * 128 + f] * cnorm[e];
    }
    float di = dinv[v];
    acc += xw[(size_t)v * 128 + f] * (di * di);   // self-loop
    acc += bias[f];
    out[(size_t)v * 128 + f] = fmaxf(acc, 0.f);
}

// ---------------- mean-pool: block per segment ----------------
__global__ void pool_agg_kernel(const float* __restrict__ h, float* __restrict__ z,
                                const int* __restrict__ prow, const int* __restrict__ pnode) {
    int d = blockIdx.x;
    int f = threadIdx.x;
    int beg = prow[d];
    int end = prow[d + 1];
    float acc = 0.f;
    for (int m = beg; m < end; m++)
        acc += h[(size_t)pnode[m] * 128 + f];
    float c = (float)(end - beg);
    z[(size_t)d * 128 + f] = acc / fmaxf(c, 1.f);
}

// ---------------- decode: warp per edge, dot over 128 dims ----------------
__global__ void decode_kernel(const float* __restrict__ z,
                              const void* __restrict__ pos,
                              const void* __restrict__ neg,
                              const int* __restrict__ flag,
                              float* __restrict__ out, int ep) {
    int is64 = flag[0];
    int gw = (blockIdx.x * blockDim.x + threadIdx.x) >> 5;
    int lane = threadIdx.x & 31;
    int total = 2 * ep;
    if (gw >= total) return;
    int a, b;
    if (gw < ep) { a = idx_at(pos, gw, is64); b = idx_at(pos, (long long)ep + gw, is64); }
    else { int e = gw - ep; a = idx_at(neg, e, is64); b = idx_at(neg, (long long)ep + e, is64); }
    const float4* za = reinterpret_cast<const float4*>(z + (size_t)a * 128);
    const float4* zb = reinterpret_cast<const float4*>(z + (size_t)b * 128);
    float4 xa = za[lane];
    float4 xb = zb[lane];
    float s = xa.x * xb.x + xa.y * xb.y + xa.z * xb.z + xa.w * xb.w;
    s += __shfl_xor_sync(0xffffffffu, s, 16);
    s += __shfl_xor_sync(0xffffffffu, s, 8);
    s += __shfl_xor_sync(0xffffffffu, s, 4);
    s += __shfl_xor_sync(0xffffffffu, s, 2);
    s += __shfl_xor_sync(0xffffffffu, s, 1);
    if (lane == 0) out[gw] = s;
}

// ---------------- launch ----------------
extern "C" void kernel_launch(void* const* d_in, const int* in_sizes, int n_in,
                              void* d_out, int out_size) {
    const float* x  = (const float*)d_in[0];
    const float* W1 = (const float*)d_in[1];
    const float* b1 = (const float*)d_in[2];
    const float* W2 = (const float*)d_in[3];
    const float* b2 = (const float*)d_in[4];
    const void*  edge = d_in[5];
    const void*  dict = d_in[6];
    const void*  pos  = d_in[7];
    const void*  neg  = d_in[8];
    float* out = (float*)d_out;

    const int n  = in_sizes[0] / HH;     // 100000
    const int ne = in_sizes[5] / 2;      // 1600000 (element count halved; dtype-independent)
    const int ep = in_sizes[7] / 2;      // 200000

    float *xw, *h1, *h2, *dinv, *cnorm;
    int *cnt, *fill, *rowptr, *bsums, *csrc, *pcnt, *pfill, *prow, *pnode, *flag;
    cudaGetSymbolAddress((void**)&xw,    g_xw);
    cudaGetSymbolAddress((void**)&h1,    g_h1);
    cudaGetSymbolAddress((void**)&h2,    g_h2);
    cudaGetSymbolAddress((void**)&dinv,  g_dinv);
    cudaGetSymbolAddress((void**)&cnorm, g_cnorm);
    cudaGetSymbolAddress((void**)&cnt,   g_cnt);
    cudaGetSymbolAddress((void**)&fill,  g_fill);
    cudaGetSymbolAddress((void**)&rowptr,g_rowptr);
    cudaGetSymbolAddress((void**)&bsums, g_bsums);
    cudaGetSymbolAddress((void**)&csrc,  g_csrc);
    cudaGetSymbolAddress((void**)&pcnt,  g_pcnt);
    cudaGetSymbolAddress((void**)&pfill, g_pfill);
    cudaGetSymbolAddress((void**)&prow,  g_prow);
    cudaGetSymbolAddress((void**)&pnode, g_pnode);
    cudaGetSymbolAddress((void**)&flag,  g_is64);

    const int nb1024 = (n + 1023) / 1024;  // 98

    // 0) detect index dtype (int32 vs int64)
    detect_kernel<<<1, 256>>>(edge, flag);
    // 1) reset counters
    zero_counts_kernel<<<(n + 255) / 256, 256>>>(cnt, fill, pcnt, pfill, n);
    // 2) degree histogram (dst half of edge_index) + pool-segment histogram
    hist_kernel<<<(ne + 255) / 256, 256>>>(edge, (long long)ne, flag, cnt, ne);
    hist_kernel<<<(n + 255) / 256, 256>>>(dict, 0LL, flag, pcnt, n);
    // 3) symmetric-norm 1/sqrt(deg)
    dinv_kernel<<<(n + 255) / 256, 256>>>(cnt, dinv, n);
    // 4) edge CSR rowptr
    scan1_kernel<<<nb1024, 1024>>>(cnt, rowptr, bsums, n);
    scan2_kernel<<<1, 32>>>(bsums, nb1024, rowptr, n);
    scan3_kernel<<<(n + 255) / 256, 256>>>(rowptr, bsums, n);
    // 5) pool CSR rowptr (reuses bsums; same stream, strictly ordered)
    scan1_kernel<<<nb1024, 1024>>>(pcnt, prow, bsums, n);
    scan2_kernel<<<1, 32>>>(bsums, nb1024, prow, n);
    scan3_kernel<<<(n + 255) / 256, 256>>>(prow, bsums, n);
    // 6) scatter edges + pool members into CSR
    scatter_edges_kernel<<<(ne + 255) / 256, 256>>>(edge, (long long)ne, flag, rowptr, fill, csrc, cnorm, dinv, ne);
    scatter_pool_kernel<<<(n + 255) / 256, 256>>>(dict, flag, prow, pfill, pnode, n);

    const int gemm_blocks = (n + BM - 1) / BM;
    // 7) layer 1
    gemm128_kernel<<<gemm_blocks, 256>>>(x, W1, xw, n);
    agg_kernel<<<n, 128>>>(xw, h1, b1, rowptr, csrc, cnorm, dinv);
    // 8) layer 2
    gemm128_kernel<<<gemm_blocks, 256>>>(h1, W2, xw, n);
    agg_kernel<<<n, 128>>>(xw, h2, b2, rowptr, csrc, cnorm, dinv);
    // 9) mean pool (z into h1, free by now)
    pool_agg_kernel<<<n, 128>>>(h2, h1, prow, pnode);
    // 10) decode
    int total_warps = 2 * ep;
    int dec_blocks = (total_warps * 32 + 255) / 256;
    decode_kernel<<<dec_blocks, 256>>>(h1, pos, neg, flag, out, ep);
}

// round 3
// speedup vs baseline: 1.1471x; 1.1471x over previous
#include <cuda_runtime.h>
#include <cuda_bf16.h>
#include <mma.h>
#include <cstdint>
#include <cstddef>

using namespace nvcuda;

#define NN 100000
#define NN_PAD 100096           // multiple of 128 for tail-free GEMM stores
#define HH 128
#define EE 1600000
#define EPP 200000

// ---------------- scratch (device globals; no allocation allowed) ----------------
__device__ float g_xw[(size_t)NN_PAD * HH];
__device__ float g_h1[(size_t)NN_PAD * HH];
__device__ float g_h2[(size_t)NN_PAD * HH];
__device__ float g_dinv[NN];
__device__ float g_cnorm[EE];
__device__ int   g_cnt[NN];
__device__ int   g_fill[NN];
__device__ int   g_rowptr[NN + 1];
__device__ int   g_bsums[256];
__device__ int   g_csrc[EE];
__device__ int   g_pcnt[NN];
__device__ int   g_pfill[NN];
__device__ int   g_prow[NN + 1];
__device__ int   g_pnode[NN];
__device__ int   g_is64[1];

// ---------------- index dtype detection + accessor ----------------
__global__ void detect_kernel(const void* __restrict__ p, int* __restrict__ flag) {
    const int2* q = (const int2*)p;
    __shared__ int any_hi;
    if (threadIdx.x == 0) any_hi = 0;
    __syncthreads();
    for (int i = threadIdx.x; i < 1024; i += blockDim.x)
        if (q[i].y != 0) any_hi = 1;
    __syncthreads();
    if (threadIdx.x == 0) flag[0] = any_hi ? 0 : 1;   // 1 => int64
}

__device__ __forceinline__ int idx_at(const void* __restrict__ p, long long i, int is64) {
    if (is64) return (int)((const long long*)p)[i];
    return ((const int*)p)[i];
}

// ---------------- small utility kernels ----------------
__global__ void zero_counts_kernel(int* cnt, int* fill, int* pcnt, int* pfill, int n) {
    int i = blockIdx.x * blockDim.x + threadIdx.x;
    if (i < n) { cnt[i] = 0; fill[i] = 0; pcnt[i] = 0; pfill[i] = 0; }
}

__global__ void hist_kernel(const void* __restrict__ idx, long long base,
                            const int* __restrict__ flag, int* __restrict__ cnt, int n) {
    int is64 = flag[0];
    int i = blockIdx.x * blockDim.x + threadIdx.x;
    int stride = gridDim.x * blockDim.x;
    for (; i < n; i += stride) atomicAdd(&cnt[idx_at(idx, base + i, is64)], 1);
}

__global__ void dinv_kernel(const int* __restrict__ cnt, float* __restrict__ dinv, int n) {
    int i = blockIdx.x * blockDim.x + threadIdx.x;
    if (i < n) dinv[i] = rsqrtf((float)(cnt[i] + 1));   // +1 self-loop
}

// ---------------- exclusive scan (3-phase, 1024 elems/block) ----------------
__global__ void scan1_kernel(const int* __restrict__ cnt, int* __restrict__ rp,
                             int* __restrict__ bs, int n) {
    __shared__ int sh[1024];
    int tid = threadIdx.x;
    int i = blockIdx.x * 1024 + tid;
    int v = (i < n) ? cnt[i] : 0;
    sh[tid] = v;
    __syncthreads();
    #pragma unroll
    for (int off = 1; off < 1024; off <<= 1) {
        int t = (tid >= off) ? sh[tid - off] : 0;
        __syncthreads();
        sh[tid] += t;
        __syncthreads();
    }
    if (i < n) rp[i] = sh[tid] - v;
    if (tid == 1023) bs[blockIdx.x] = sh[1023];
}

__global__ void scan2_kernel(int* bs, int nb, int* rp, int n) {
    if (threadIdx.x == 0 && blockIdx.x == 0) {
        int run = 0;
        for (int b = 0; b < nb; b++) { int t = bs[b]; bs[b] = run; run += t; }
        rp[n] = run;
    }
}

__global__ void scan3_kernel(int* rp, const int* __restrict__ bs, int n) {
    int i = blockIdx.x * blockDim.x + threadIdx.x;
    if (i < n) rp[i] += bs[i >> 10];
}

// ---------------- CSR scatter ----------------
__global__ void scatter_edges_kernel(const void* __restrict__ edge, long long ne,
                                     const int* __restrict__ flag,
                                     const int* __restrict__ rowptr, int* __restrict__ fill,
                                     int* __restrict__ csrc, float* __restrict__ cnorm,
                                     const float* __restrict__ dinv, int n) {
    int is64 = flag[0];
    int e = blockIdx.x * blockDim.x + threadIdx.x;
    int stride = gridDim.x * blockDim.x;
    for (; e < n; e += stride) {
        int s = idx_at(edge, e, is64);
        int d = idx_at(edge, ne + e, is64);
        int p = rowptr[d] + atomicAdd(&fill[d], 1);
        csrc[p] = s;
        cnorm[p] = dinv[s] * dinv[d];
    }
}

__global__ void scatter_pool_kernel(const void* __restrict__ dict,
                                    const int* __restrict__ flag,
                                    const int* __restrict__ prow, int* __restrict__ pfill,
                                    int* __restrict__ pnode, int n) {
    int is64 = flag[0];
    int v = blockIdx.x * blockDim.x + threadIdx.x;
    if (v < n) {
        int d = idx_at(dict, v, is64);
        int p = prow[d] + atomicAdd(&pfill[d], 1);
        pnode[p] = v;
    }
}

// ---------------- tf32 tensor-core GEMM: C[n_pad,128] = A[n,128] @ W[128,128] ----
// Block tile 128x128, BK=32, 8 warps in 4(M) x 2(N), warp tile 32x64
// via 2x4 m16n16k8 tf32 WMMA fragments. C stores are tail-free (padded scratch).
__global__ void gemm_tf32_kernel(const float* __restrict__ A, const float* __restrict__ W,
                                 float* __restrict__ C, int n) {
    __shared__ __align__(16) float As[128][36];
    __shared__ __align__(16) float Ws[32][132];
    int tid = threadIdx.x;
    int warpId = tid >> 5;
    int wm = warpId & 3;       // 0..3 -> M offset wm*32
    int wn = warpId >> 2;      // 0..1 -> N offset wn*64
    int row0 = blockIdx.x * 128;

    wmma::fragment<wmma::accumulator, 16, 16, 8, float> acc[2][4];
    #pragma unroll
    for (int i = 0; i < 2; i++)
        #pragma unroll
        for (int j = 0; j < 4; j++) wmma::fill_fragment(acc[i][j], 0.0f);

    for (int kt = 0; kt < 128; kt += 32) {
        // stage A tile 128x32 (zero-fill rows >= n), convert to tf32
        #pragma unroll
        for (int p = 0; p < 4; p++) {
            int i = tid + p * 256;            // 0..1023 float4 slots
            int r = i >> 3;                   // row 0..127
            int c4 = (i & 7) * 4;             // col 0,4,..,28
            float4 v = make_float4(0.f, 0.f, 0.f, 0.f);
            int gr = row0 + r;
            if (gr < n)
                v = *reinterpret_cast<const float4*>(A + (size_t)gr * 128 + kt + c4);
            As[r][c4 + 0] = wmma::__float_to_tf32(v.x);
            As[r][c4 + 1] = wmma::__float_to_tf32(v.y);
            As[r][c4 + 2] = wmma::__float_to_tf32(v.z);
            As[r][c4 + 3] = wmma::__float_to_tf32(v.w);
        }
        // stage W tile 32x128, convert to tf32
        #pragma unroll
        for (int p = 0; p < 4; p++) {
            int i = tid + p * 256;
            int r = i >> 5;                   // row 0..31
            int c4 = (i & 31) * 4;            // col 0..124
            float4 v = *reinterpret_cast<const float4*>(W + (size_t)(kt + r) * 128 + c4);
            Ws[r][c4 + 0] = wmma::__float_to_tf32(v.x);
            Ws[r][c4 + 1] = wmma::__float_to_tf32(v.y);
            Ws[r][c4 + 2] = wmma::__float_to_tf32(v.z);
            Ws[r][c4 + 3] = wmma::__float_to_tf32(v.w);
        }
        __syncthreads();
        #pragma unroll
        for (int kk = 0; kk < 4; kk++) {
            wmma::fragment<wmma::matrix_a, 16, 16, 8, wmma::precision::tf32, wmma::row_major> af[2];
            wmma::fragment<wmma::matrix_b, 16, 16, 8, wmma::precision::tf32, wmma::row_major> bf[4];
            #pragma unroll
            for (int i = 0; i < 2; i++)
                wmma::load_matrix_sync(af[i], &As[wm * 32 + i * 16][kk * 8], 36);
            #pragma unroll
            for (int j = 0; j < 4; j++)
                wmma::load_matrix_sync(bf[j], &Ws[kk * 8][wn * 64 + j * 16], 132);
            #pragma unroll
            for (int i = 0; i < 2; i++)
                #pragma unroll
                for (int j = 0; j < 4; j++)
                    wmma::mma_sync(acc[i][j], af[i], bf[j], acc[i][j]);
        }
        __syncthreads();
    }
    // store (C is padded to a multiple of 128 rows -> no bounds checks)
    #pragma unroll
    for (int i = 0; i < 2; i++)
        #pragma unroll
        for (int j = 0; j < 4; j++)
            wmma::store_matrix_sync(C + (size_t)(row0 + wm * 32 + i * 16) * 128 + wn * 64 + j * 16,
                                    acc[i][j], 128, wmma::mem_row_major);
}

// ---------------- GCN aggregation: block per dst node, thread per feature ----------------
__global__ void agg_kernel(const float* __restrict__ xw, float* __restrict__ out,
                           const float* __restrict__ bias,
                           const int* __restrict__ rowptr, const int* __restrict__ csrc,
                           const float* __restrict__ cnorm, const float* __restrict__ dinv) {
    int v = blockIdx.x;
    int f = threadIdx.x;
    int beg = rowptr[v];
    int end = rowptr[v + 1];
    float acc = 0.f;
    int e = beg;
    for (; e + 1 < end; e += 2) {
        int s0 = csrc[e];
        int s1 = csrc[e + 1];
        float n0 = cnorm[e];
        float n1 = cnorm[e + 1];
        float x0 = xw[(size_t)s0 * 128 + f];
        float x1 = xw[(size_t)s1 * 128 + f];
        acc += x0 * n0 + x1 * n1;
    }
    if (e < end) {
        int s = csrc[e];
        acc += xw[(size_t)s * 128 + f] * cnorm[e];
    }
    float di = dinv[v];
    acc += xw[(size_t)v * 128 + f] * (di * di);   // self-loop
    acc += bias[f];
    out[(size_t)v * 128 + f] = fmaxf(acc, 0.f);
}

// ---------------- mean-pool: block per segment ----------------
__global__ void pool_agg_kernel(const float* __restrict__ h, float* __restrict__ z,
                                const int* __restrict__ prow, const int* __restrict__ pnode) {
    int d = blockIdx.x;
    int f = threadIdx.x;
    int beg = prow[d];
    int end = prow[d + 1];
    float acc = 0.f;
    for (int m = beg; m < end; m++)
        acc += h[(size_t)pnode[m] * 128 + f];
    float c = (float)(end - beg);
    z[(size_t)d * 128 + f] = acc / fmaxf(c, 1.f);
}

// ---------------- decode: warp per edge, dot over 128 dims ----------------
__global__ void decode_kernel(const float* __restrict__ z,
                              const void* __restrict__ pos,
                              const void* __restrict__ neg,
                              const int* __restrict__ flag,
                              float* __restrict__ out, int ep) {
    int is64 = flag[0];
    int gw = (blockIdx.x * blockDim.x + threadIdx.x) >> 5;
    int lane = threadIdx.x & 31;
    int total = 2 * ep;
    if (gw >= total) return;
    int a, b;
    if (gw < ep) { a = idx_at(pos, gw, is64); b = idx_at(pos, (long long)ep + gw, is64); }
    else { int e = gw - ep; a = idx_at(neg, e, is64); b = idx_at(neg, (long long)ep + e, is64); }
    const float4* za = reinterpret_cast<const float4*>(z + (size_t)a * 128);
    const float4* zb = reinterpret_cast<const float4*>(z + (size_t)b * 128);
    float4 xa = za[lane];
    float4 xb = zb[lane];
    float s = xa.x * xb.x + xa.y * xb.y + xa.z * xb.z + xa.w * xb.w;
    s += __shfl_xor_sync(0xffffffffu, s, 16);
    s += __shfl_xor_sync(0xffffffffu, s, 8);
    s += __shfl_xor_sync(0xffffffffu, s, 4);
    s += __shfl_xor_sync(0xffffffffu, s, 2);
    s += __shfl_xor_sync(0xffffffffu, s, 1);
    if (lane == 0) out[gw] = s;
}

// ---------------- launch ----------------
extern "C" void kernel_launch(void* const* d_in, const int* in_sizes, int n_in,
                              void* d_out, int out_size) {
    const float* x  = (const float*)d_in[0];
    const float* W1 = (const float*)d_in[1];
    const float* b1 = (const float*)d_in[2];
    const float* W2 = (const float*)d_in[3];
    const float* b2 = (const float*)d_in[4];
    const void*  edge = d_in[5];
    const void*  dict = d_in[6];
    const void*  pos  = d_in[7];
    const void*  neg  = d_in[8];
    float* out = (float*)d_out;

    const int n  = in_sizes[0] / HH;     // 100000
    const int ne = in_sizes[5] / 2;      // 1600000
    const int ep = in_sizes[7] / 2;      // 200000

    float *xw, *h1, *h2, *dinv, *cnorm;
    int *cnt, *fill, *rowptr, *bsums, *csrc, *pcnt, *pfill, *prow, *pnode, *flag;
    cudaGetSymbolAddress((void**)&xw,    g_xw);
    cudaGetSymbolAddress((void**)&h1,    g_h1);
    cudaGetSymbolAddress((void**)&h2,    g_h2);
    cudaGetSymbolAddress((void**)&dinv,  g_dinv);
    cudaGetSymbolAddress((void**)&cnorm, g_cnorm);
    cudaGetSymbolAddress((void**)&cnt,   g_cnt);
    cudaGetSymbolAddress((void**)&fill,  g_fill);
    cudaGetSymbolAddress((void**)&rowptr,g_rowptr);
    cudaGetSymbolAddress((void**)&bsums, g_bsums);
    cudaGetSymbolAddress((void**)&csrc,  g_csrc);
    cudaGetSymbolAddress((void**)&pcnt,  g_pcnt);
    cudaGetSymbolAddress((void**)&pfill, g_pfill);
    cudaGetSymbolAddress((void**)&prow,  g_prow);
    cudaGetSymbolAddress((void**)&pnode, g_pnode);
    cudaGetSymbolAddress((void**)&flag,  g_is64);

    const int nb1024 = (n + 1023) / 1024;  // 98

    // 0) detect index dtype (int32 vs int64)
    detect_kernel<<<1, 256>>>(edge, flag);
    // 1) reset counters
    zero_counts_kernel<<<(n + 255) / 256, 256>>>(cnt, fill, pcnt, pfill, n);
    // 2) degree histogram (dst half) + pool-segment histogram
    hist_kernel<<<(ne + 255) / 256, 256>>>(edge, (long long)ne, flag, cnt, ne);
    hist_kernel<<<(n + 255) / 256, 256>>>(dict, 0LL, flag, pcnt, n);
    // 3) symmetric-norm 1/sqrt(deg)
    dinv_kernel<<<(n + 255) / 256, 256>>>(cnt, dinv, n);
    // 4) edge CSR rowptr
    scan1_kernel<<<nb1024, 1024>>>(cnt, rowptr, bsums, n);
    scan2_kernel<<<1, 32>>>(bsums, nb1024, rowptr, n);
    scan3_kernel<<<(n + 255) / 256, 256>>>(rowptr, bsums, n);
    // 5) pool CSR rowptr
    scan1_kernel<<<nb1024, 1024>>>(pcnt, prow, bsums, n);
    scan2_kernel<<<1, 32>>>(bsums, nb1024, prow, n);
    scan3_kernel<<<(n + 255) / 256, 256>>>(prow, bsums, n);
    // 6) scatter edges + pool members into CSR
    scatter_edges_kernel<<<(ne + 255) / 256, 256>>>(edge, (long long)ne, flag, rowptr, fill, csrc, cnorm, dinv, ne);
    scatter_pool_kernel<<<(n + 255) / 256, 256>>>(dict, flag, prow, pfill, pnode, n);

    const int gemm_blocks = (n + 127) / 128;  // 782
    // 7) layer 1 (tf32 tensor cores)
    gemm_tf32_kernel<<<gemm_blocks, 256>>>(x, W1, xw, n);
    agg_kernel<<<n, 128>>>(xw, h1, b1, rowptr, csrc, cnorm, dinv);
    // 8) layer 2
    gemm_tf32_kernel<<<gemm_blocks, 256>>>(h1, W2, xw, n);
    agg_kernel<<<n, 128>>>(xw, h2, b2, rowptr, csrc, cnorm, dinv);
    // 9) mean pool (z into h1)
    pool_agg_kernel<<<n, 128>>>(h2, h1, prow, pnode);
    // 10) decode
    int total_warps = 2 * ep;
    int dec_blocks = (total_warps * 32 + 255) / 256;
    decode_kernel<<<dec_blocks, 256>>>(h1, pos, neg, flag, out, ep);
}

// round 4
// speedup vs baseline: 1.3398x; 1.1679x over previous
#include <cuda_runtime.h>
#include <cuda_fp16.h>
#include <mma.h>
#include <cstdint>
#include <cstddef>

using namespace nvcuda;

#define NN 100000
#define NN_PAD 100096           // multiple of 128 for tail-free GEMM stores
#define HH 128
#define EE 1600000
#define EPP 200000

// ---------------- scratch (device globals; no allocation allowed) ----------------
__device__ __half g_xw[(size_t)NN_PAD * HH];   // GEMM output (fp16, gathered by agg)
__device__ __half g_h1[(size_t)NN_PAD * HH];   // layer-1 activations (fp16, GEMM2 input)
__device__ float  g_h2[(size_t)NN * HH];       // layer-2 activations (fp32)
__device__ float  g_z[(size_t)NN * HH];        // pooled embeddings (fp32)
__device__ float  g_dinv[NN];
__device__ float  g_cnorm[EE];
__device__ int    g_cnt[NN];
__device__ int    g_fill[NN];
__device__ int    g_rowptr[NN + 1];
__device__ int    g_bsums[256];
__device__ int    g_csrc[EE];
__device__ int    g_pcnt[NN];
__device__ int    g_pfill[NN];
__device__ int    g_prow[NN + 1];
__device__ int    g_pnode[NN];
__device__ int    g_is64[1];

// ---------------- index dtype detection + accessor ----------------
__global__ void detect_kernel(const void* __restrict__ p, int* __restrict__ flag) {
    const int2* q = (const int2*)p;
    __shared__ int any_hi;
    if (threadIdx.x == 0) any_hi = 0;
    __syncthreads();
    for (int i = threadIdx.x; i < 1024; i += blockDim.x)
        if (q[i].y != 0) any_hi = 1;
    __syncthreads();
    if (threadIdx.x == 0) flag[0] = any_hi ? 0 : 1;   // 1 => int64
}

__device__ __forceinline__ int idx_at(const void* __restrict__ p, long long i, int is64) {
    if (is64) return (int)((const long long*)p)[i];
    return ((const int*)p)[i];
}

// ---------------- small utility kernels ----------------
__global__ void zero_counts_kernel(int* cnt, int* fill, int* pcnt, int* pfill, int n) {
    int i = blockIdx.x * blockDim.x + threadIdx.x;
    if (i < n) { cnt[i] = 0; fill[i] = 0; pcnt[i] = 0; pfill[i] = 0; }
}

__global__ void hist_kernel(const void* __restrict__ idx, long long base,
                            const int* __restrict__ flag, int* __restrict__ cnt, int n) {
    int is64 = flag[0];
    int i = blockIdx.x * blockDim.x + threadIdx.x;
    int stride = gridDim.x * blockDim.x;
    for (; i < n; i += stride) atomicAdd(&cnt[idx_at(idx, base + i, is64)], 1);
}

__global__ void dinv_kernel(const int* __restrict__ cnt, float* __restrict__ dinv, int n) {
    int i = blockIdx.x * blockDim.x + threadIdx.x;
    if (i < n) dinv[i] = rsqrtf((float)(cnt[i] + 1));   // +1 self-loop
}

// ---------------- exclusive scan (3-phase, 1024 elems/block) ----------------
__global__ void scan1_kernel(const int* __restrict__ cnt, int* __restrict__ rp,
                             int* __restrict__ bs, int n) {
    __shared__ int sh[1024];
    int tid = threadIdx.x;
    int i = blockIdx.x * 1024 + tid;
    int v = (i < n) ? cnt[i] : 0;
    sh[tid] = v;
    __syncthreads();
    #pragma unroll
    for (int off = 1; off < 1024; off <<= 1) {
        int t = (tid >= off) ? sh[tid - off] : 0;
        __syncthreads();
        sh[tid] += t;
        __syncthreads();
    }
    if (i < n) rp[i] = sh[tid] - v;
    if (tid == 1023) bs[blockIdx.x] = sh[1023];
}

__global__ void scan2_kernel(int* bs, int nb, int* rp, int n) {
    if (threadIdx.x == 0 && blockIdx.x == 0) {
        int run = 0;
        for (int b = 0; b < nb; b++) { int t = bs[b]; bs[b] = run; run += t; }
        rp[n] = run;
    }
}

__global__ void scan3_kernel(int* rp, const int* __restrict__ bs, int n) {
    int i = blockIdx.x * blockDim.x + threadIdx.x;
    if (i < n) rp[i] += bs[i >> 10];
}

// ---------------- CSR scatter ----------------
__global__ void scatter_edges_kernel(const void* __restrict__ edge, long long ne,
                                     const int* __restrict__ flag,
                                     const int* __restrict__ rowptr, int* __restrict__ fill,
                                     int* __restrict__ csrc, float* __restrict__ cnorm,
                                     const float* __restrict__ dinv, int n) {
    int is64 = flag[0];
    int e = blockIdx.x * blockDim.x + threadIdx.x;
    int stride = gridDim.x * blockDim.x;
    for (; e < n; e += stride) {
        int s = idx_at(edge, e, is64);
        int d = idx_at(edge, ne + e, is64);
        int p = rowptr[d] + atomicAdd(&fill[d], 1);
        csrc[p] = s;
        cnorm[p] = dinv[s] * dinv[d];
    }
}

__global__ void scatter_pool_kernel(const void* __restrict__ dict,
                                    const int* __restrict__ flag,
                                    const int* __restrict__ prow, int* __restrict__ pfill,
                                    int* __restrict__ pnode, int n) {
    int is64 = flag[0];
    int v = blockIdx.x * blockDim.x + threadIdx.x;
    if (v < n) {
        int d = idx_at(dict, v, is64);
        int p = prow[d] + atomicAdd(&pfill[d], 1);
        pnode[p] = v;
    }
}

// ---------------- tf32 tensor-core GEMM -> fp16 output ----------------
// C[n_pad,128](fp16) = A[n,128] @ W[128,128]. Block tile 128x128, BK=32,
// 8 warps 4(M)x2(N), warp tile 32x64 via 2x4 m16n16k8 tf32 fragments.
// Epilogue: accumulators -> smem (reused) -> fp16 global, two N-half passes.
template <bool A_HALF>
__global__ void gemm_tf32_kernel(const void* __restrict__ Av, const float* __restrict__ W,
                                 __half* __restrict__ C, int n) {
    __shared__ __align__(16) float smemBuf[128 * 36 + 32 * 132];   // 8832 floats
    float (*As)[36]  = reinterpret_cast<float(*)[36]>(smemBuf);
    float (*Ws)[132] = reinterpret_cast<float(*)[132]>(smemBuf + 128 * 36);
    int tid = threadIdx.x;
    int warpId = tid >> 5;
    int wm = warpId & 3;
    int wn = warpId >> 2;
    int row0 = blockIdx.x * 128;

    wmma::fragment<wmma::accumulator, 16, 16, 8, float> acc[2][4];
    #pragma unroll
    for (int i = 0; i < 2; i++)
        #pragma unroll
        for (int j = 0; j < 4; j++) wmma::fill_fragment(acc[i][j], 0.0f);

    for (int kt = 0; kt < 128; kt += 32) {
        // stage A tile 128x32 (zero rows >= n), convert to tf32
        #pragma unroll
        for (int p = 0; p < 4; p++) {
            int i = tid + p * 256;
            int r = i >> 3;
            int c4 = (i & 7) * 4;
            int gr = row0 + r;
            float f0 = 0.f, f1 = 0.f, f2 = 0.f, f3 = 0.f;
            if (gr < n) {
                if (A_HALF) {
                    const __half* Ah = (const __half*)Av;
                    uint2 v = *reinterpret_cast<const uint2*>(Ah + (size_t)gr * 128 + kt + c4);
                    half2 h0 = *reinterpret_cast<half2*>(&v.x);
                    half2 h1 = *reinterpret_cast<half2*>(&v.y);
                    float2 a = __half22float2(h0), b = __half22float2(h1);
                    f0 = a.x; f1 = a.y; f2 = b.x; f3 = b.y;
                } else {
                    const float* Af = (const float*)Av;
                    float4 v = *reinterpret_cast<const float4*>(Af + (size_t)gr * 128 + kt + c4);
                    f0 = v.x; f1 = v.y; f2 = v.z; f3 = v.w;
                }
            }
            As[r][c4 + 0] = wmma::__float_to_tf32(f0);
            As[r][c4 + 1] = wmma::__float_to_tf32(f1);
            As[r][c4 + 2] = wmma::__float_to_tf32(f2);
            As[r][c4 + 3] = wmma::__float_to_tf32(f3);
        }
        // stage W tile 32x128
        #pragma unroll
        for (int p = 0; p < 4; p++) {
            int i = tid + p * 256;
            int r = i >> 5;
            int c4 = (i & 31) * 4;
            float4 v = *reinterpret_cast<const float4*>(W + (size_t)(kt + r) * 128 + c4);
            Ws[r][c4 + 0] = wmma::__float_to_tf32(v.x);
            Ws[r][c4 + 1] = wmma::__float_to_tf32(v.y);
            Ws[r][c4 + 2] = wmma::__float_to_tf32(v.z);
            Ws[r][c4 + 3] = wmma::__float_to_tf32(v.w);
        }
        __syncthreads();
        #pragma unroll
        for (int kk = 0; kk < 4; kk++) {
            wmma::fragment<wmma::matrix_a, 16, 16, 8, wmma::precision::tf32, wmma::row_major> af[2];
            wmma::fragment<wmma::matrix_b, 16, 16, 8, wmma::precision::tf32, wmma::row_major> bf[4];
            #pragma unroll
            for (int i = 0; i < 2; i++)
                wmma::load_matrix_sync(af[i], &As[wm * 32 + i * 16][kk * 8], 36);
            #pragma unroll
            for (int j = 0; j < 4; j++)
                wmma::load_matrix_sync(bf[j], &Ws[kk * 8][wn * 64 + j * 16], 132);
            #pragma unroll
            for (int i = 0; i < 2; i++)
                #pragma unroll
                for (int j = 0; j < 4; j++)
                    wmma::mma_sync(acc[i][j], af[i], bf[j], acc[i][j]);
        }
        __syncthreads();
    }
    // epilogue: two passes (N halves), reuse smemBuf as 128x64 fp32 (stride 64)
    int er = tid >> 1;
    int ec0 = (tid & 1) * 32;
    #pragma unroll
    for (int p = 0; p < 2; p++) {
        if (wn == p) {
            #pragma unroll
            for (int i = 0; i < 2; i++)
                #pragma unroll
                for (int j = 0; j < 4; j++)
                    wmma::store_matrix_sync(&smemBuf[(wm * 32 + i * 16) * 64 + j * 16],
                                            acc[i][j], 64, wmma::mem_row_major);
        }
        __syncthreads();
        const float* src = smemBuf + er * 64 + ec0;
        __half* dst = C + (size_t)(row0 + er) * 128 + p * 64 + ec0;
        #pragma unroll
        for (int k = 0; k < 32; k += 2) {
            half2 h = __floats2half2_rn(src[k], src[k + 1]);
            *reinterpret_cast<half2*>(dst + k) = h;
        }
        __syncthreads();
    }
}

// ---------------- store helpers ----------------
__device__ __forceinline__ void store4(float* p, float a0, float a1, float a2, float a3) {
    *reinterpret_cast<float4*>(p) = make_float4(a0, a1, a2, a3);
}
__device__ __forceinline__ void store4(__half* p, float a0, float a1, float a2, float a3) {
    half2 h0 = __floats2half2_rn(a0, a1);
    half2 h1 = __floats2half2_rn(a2, a3);
    uint2 u;
    u.x = *reinterpret_cast<unsigned*>(&h0);
    u.y = *reinterpret_cast<unsigned*>(&h1);
    *reinterpret_cast<uint2*>(p) = u;
}

// ---------------- GCN aggregation: warp per dst node, lane = 4 features ----------------
template <typename OutT>
__global__ void agg_warp_kernel(const __half* __restrict__ xw, OutT* __restrict__ out,
                                const float* __restrict__ bias,
                                const int* __restrict__ rowptr, const int* __restrict__ csrc,
                                const float* __restrict__ cnorm, const float* __restrict__ dinv,
                                int n) {
    int w = (blockIdx.x * blockDim.x + threadIdx.x) >> 5;
    int lane = threadIdx.x & 31;
    if (w >= n) return;
    int beg = rowptr[w];
    int end = rowptr[w + 1];
    size_t loff = (size_t)lane * 4;
    float a0 = 0.f, a1 = 0.f, a2 = 0.f, a3 = 0.f;
    #pragma unroll 4
    for (int e = beg; e < end; e++) {
        int s = __ldg(csrc + e);
        float nm = __ldg(cnorm + e);
        uint2 v = *reinterpret_cast<const uint2*>(xw + (size_t)s * 128 + loff);
        half2 h0 = *reinterpret_cast<half2*>(&v.x);
        half2 h1 = *reinterpret_cast<half2*>(&v.y);
        float2 f0 = __half22float2(h0), f1 = __half22float2(h1);
        a0 += f0.x * nm; a1 += f0.y * nm; a2 += f1.x * nm; a3 += f1.y * nm;
    }
    float di = dinv[w];
    float sw = di * di;
    {
        uint2 v = *reinterpret_cast<const uint2*>(xw + (size_t)w * 128 + loff);
        half2 h0 = *reinterpret_cast<half2*>(&v.x);
        half2 h1 = *reinterpret_cast<half2*>(&v.y);
        float2 f0 = __half22float2(h0), f1 = __half22float2(h1);
        a0 += f0.x * sw; a1 += f0.y * sw; a2 += f1.x * sw; a3 += f1.y * sw;
    }
    float4 bb = *reinterpret_cast<const float4*>(bias + loff);
    a0 = fmaxf(a0 + bb.x, 0.f);
    a1 = fmaxf(a1 + bb.y, 0.f);
    a2 = fmaxf(a2 + bb.z, 0.f);
    a3 = fmaxf(a3 + bb.w, 0.f);
    store4(out + (size_t)w * 128 + loff, a0, a1, a2, a3);
}

// ---------------- mean-pool: block per segment (fp32 in/out) ----------------
__global__ void pool_agg_kernel(const float* __restrict__ h, float* __restrict__ z,
                                const int* __restrict__ prow, const int* __restrict__ pnode) {
    int d = blockIdx.x;
    int f = threadIdx.x;
    int beg = prow[d];
    int end = prow[d + 1];
    float acc = 0.f;
    for (int m = beg; m < end; m++)
        acc += h[(size_t)pnode[m] * 128 + f];
    float c = (float)(end - beg);
    z[(size_t)d * 128 + f] = acc / fmaxf(c, 1.f);
}

// ---------------- decode: warp per edge, dot over 128 dims (fp32) ----------------
__global__ void decode_kernel(const float* __restrict__ z,
                              const void* __restrict__ pos,
                              const void* __restrict__ neg,
                              const int* __restrict__ flag,
                              float* __restrict__ out, int ep) {
    int is64 = flag[0];
    int gw = (blockIdx.x * blockDim.x + threadIdx.x) >> 5;
    int lane = threadIdx.x & 31;
    int total = 2 * ep;
    if (gw >= total) return;
    int a, b;
    if (gw < ep) { a = idx_at(pos, gw, is64); b = idx_at(pos, (long long)ep + gw, is64); }
    else { int e = gw - ep; a = idx_at(neg, e, is64); b = idx_at(neg, (long long)ep + e, is64); }
    const float4* za = reinterpret_cast<const float4*>(z + (size_t)a * 128);
    const float4* zb = reinterpret_cast<const float4*>(z + (size_t)b * 128);
    float4 xa = za[lane];
    float4 xb = zb[lane];
    float s = xa.x * xb.x + xa.y * xb.y + xa.z * xb.z + xa.w * xb.w;
    s += __shfl_xor_sync(0xffffffffu, s, 16);
    s += __shfl_xor_sync(0xffffffffu, s, 8);
    s += __shfl_xor_sync(0xffffffffu, s, 4);
    s += __shfl_xor_sync(0xffffffffu, s, 2);
    s += __shfl_xor_sync(0xffffffffu, s, 1);
    if (lane == 0) out[gw] = s;
}

// ---------------- launch ----------------
extern "C" void kernel_launch(void* const* d_in, const int* in_sizes, int n_in,
                              void* d_out, int out_size) {
    const float* x  = (const float*)d_in[0];
    const float* W1 = (const float*)d_in[1];
    const float* b1 = (const float*)d_in[2];
    const float* W2 = (const float*)d_in[3];
    const float* b2 = (const float*)d_in[4];
    const void*  edge = d_in[5];
    const void*  dict = d_in[6];
    const void*  pos  = d_in[7];
    const void*  neg  = d_in[8];
    float* out = (float*)d_out;

    const int n  = in_sizes[0] / HH;
    const int ne = in_sizes[5] / 2;
    const int ep = in_sizes[7] / 2;

    __half *xw, *h1;
    float *h2, *z, *dinv, *cnorm;
    int *cnt, *fill, *rowptr, *bsums, *csrc, *pcnt, *pfill, *prow, *pnode, *flag;
    cudaGetSymbolAddress((void**)&xw,    g_xw);
    cudaGetSymbolAddress((void**)&h1,    g_h1);
    cudaGetSymbolAddress((void**)&h2,    g_h2);
    cudaGetSymbolAddress((void**)&z,     g_z);
    cudaGetSymbolAddress((void**)&dinv,  g_dinv);
    cudaGetSymbolAddress((void**)&cnorm, g_cnorm);
    cudaGetSymbolAddress((void**)&cnt,   g_cnt);
    cudaGetSymbolAddress((void**)&fill,  g_fill);
    cudaGetSymbolAddress((void**)&rowptr,g_rowptr);
    cudaGetSymbolAddress((void**)&bsums, g_bsums);
    cudaGetSymbolAddress((void**)&csrc,  g_csrc);
    cudaGetSymbolAddress((void**)&pcnt,  g_pcnt);
    cudaGetSymbolAddress((void**)&pfill, g_pfill);
    cudaGetSymbolAddress((void**)&prow,  g_prow);
    cudaGetSymbolAddress((void**)&pnode, g_pnode);
    cudaGetSymbolAddress((void**)&flag,  g_is64);

    const int nb1024 = (n + 1023) / 1024;

    // 0) detect index dtype
    detect_kernel<<<1, 256>>>(edge, flag);
    // 1) reset counters
    zero_counts_kernel<<<(n + 255) / 256, 256>>>(cnt, fill, pcnt, pfill, n);
    // 2) histograms
    hist_kernel<<<(ne + 255) / 256, 256>>>(edge, (long long)ne, flag, cnt, ne);
    hist_kernel<<<(n + 255) / 256, 256>>>(dict, 0LL, flag, pcnt, n);
    // 3) 1/sqrt(deg)
    dinv_kernel<<<(n + 255) / 256, 256>>>(cnt, dinv, n);
    // 4) edge CSR rowptr
    scan1_kernel<<<nb1024, 1024>>>(cnt, rowptr, bsums, n);
    scan2_kernel<<<1, 32>>>(bsums, nb1024, rowptr, n);
    scan3_kernel<<<(n + 255) / 256, 256>>>(rowptr, bsums, n);
    // 5) pool CSR rowptr
    scan1_kernel<<<nb1024, 1024>>>(pcnt, prow, bsums, n);
    scan2_kernel<<<1, 32>>>(bsums, nb1024, prow, n);
    scan3_kernel<<<(n + 255) / 256, 256>>>(prow, bsums, n);
    // 6) scatter into CSR
    scatter_edges_kernel<<<(ne + 255) / 256, 256>>>(edge, (long long)ne, flag, rowptr, fill, csrc, cnorm, dinv, ne);
    scatter_pool_kernel<<<(n + 255) / 256, 256>>>(dict, flag, prow, pfill, pnode, n);

    const int gemm_blocks = (n + 127) / 128;
    const int agg_blocks = (n + 7) / 8;           // 8 warps/block, warp per node
    // 7) layer 1
    gemm_tf32_kernel<false><<<gemm_blocks, 256>>>(x, W1, xw, n);
    agg_warp_kernel<__half><<<agg_blocks, 256>>>(xw, h1, b1, rowptr, csrc, cnorm, dinv, n);
    // 8) layer 2
    gemm_tf32_kernel<true><<<gemm_blocks, 256>>>(h1, W2, xw, n);
    agg_warp_kernel<float><<<agg_blocks, 256>>>(xw, h2, b2, rowptr, csrc, cnorm, dinv, n);
    // 9) mean pool
    pool_agg_kernel<<<n, 128>>>(h2, z, prow, pnode);
    // 10) decode
    int total_warps = 2 * ep;
    int dec_blocks = (total_warps * 32 + 255) / 256;
    decode_kernel<<<dec_blocks, 256>>>(z, pos, neg, flag, out, ep);
}

// round 5
// speedup vs baseline: 1.5888x; 1.1859x over previous
#include <cuda_runtime.h>
#include <cuda_fp16.h>
#include <mma.h>
#include <cstdint>
#include <cstddef>

using namespace nvcuda;

#define NN 100000
#define NN_PAD 100096           // multiple of 128 for tail-free GEMM stores
#define HH 128
#define EE 1600000
#define EPP 200000

// ---------------- scratch (device globals; no allocation allowed) ----------------
__device__ __half g_xw[(size_t)NN_PAD * HH];   // GEMM output (fp16, gathered by agg)
__device__ __half g_h1[(size_t)NN_PAD * HH];   // layer-1 activations (fp16, GEMM2 input)
__device__ __half g_h2[(size_t)NN * HH];       // layer-2 activations (fp16)
__device__ __half g_z[(size_t)NN * HH];        // pooled embeddings (fp16)
__device__ float  g_dinv[NN];
__device__ float  g_cnorm[EE];
__device__ int    g_cnt[NN];
__device__ int    g_fill[NN];
__device__ int    g_rowptr[NN + 1];
__device__ int    g_bsums[2 * 128];
__device__ int    g_csrc[EE];
__device__ int    g_pcnt[NN];
__device__ int    g_pfill[NN];
__device__ int    g_prow[NN + 1];
__device__ int    g_pnode[NN];
__device__ int    g_is64[1];

// ---------------- streams/events for graph fork-join (created pre-main) ----------
static cudaStream_t g_s1 = nullptr;
static cudaEvent_t  g_evA = nullptr, g_evB = nullptr;
static const bool g_init = []() {
    cudaStreamCreateWithFlags(&g_s1, cudaStreamNonBlocking);
    cudaEventCreateWithFlags(&g_evA, cudaEventDisableTiming);
    cudaEventCreateWithFlags(&g_evB, cudaEventDisableTiming);
    return true;
}();

// ---------------- index accessor ----------------
__device__ __forceinline__ int idx_at(const void* __restrict__ p, long long i, int is64) {
    if (is64) return (int)((const long long*)p)[i];
    return ((const int*)p)[i];
}

// ---------------- fused: zero counters + detect index dtype ----------------
__global__ void zero_detect_kernel(int* cnt, int* fill, int* pcnt, int* pfill, int n,
                                   const void* __restrict__ p, int* __restrict__ flag) {
    if (blockIdx.x == gridDim.x - 1) {
        // dtype detection: int64 (< 2^31) has all-zero high words; int32 doesn't.
        const int2* q = (const int2*)p;
        __shared__ int any_hi;
        if (threadIdx.x == 0) any_hi = 0;
        __syncthreads();
        for (int i = threadIdx.x; i < 1024; i += blockDim.x)
            if (q[i].y != 0) any_hi = 1;
        __syncthreads();
        if (threadIdx.x == 0) flag[0] = any_hi ? 0 : 1;
        return;
    }
    int i = blockIdx.x * blockDim.x + threadIdx.x;
    if (i < n) { cnt[i] = 0; fill[i] = 0; pcnt[i] = 0; pfill[i] = 0; }
}

// ---------------- fused histograms: edge-dst degrees + pool segments ----------------
__global__ void hist_dual_kernel(const void* __restrict__ edge, long long ne,
                                 const void* __restrict__ dict, int n,
                                 const int* __restrict__ flag,
                                 int* __restrict__ cnt, int* __restrict__ pcnt, int nbE) {
    int is64 = flag[0];
    if ((int)blockIdx.x < nbE) {
        int i = blockIdx.x * blockDim.x + threadIdx.x;
        if (i < ne) atomicAdd(&cnt[idx_at(edge, ne + i, is64)], 1);
    } else {
        int i = (blockIdx.x - nbE) * blockDim.x + threadIdx.x;
        if (i < n) atomicAdd(&pcnt[idx_at(dict, i, is64)], 1);
    }
}

// ---------------- dual exclusive scan (y=0: cnt->rowptr (+dinv), y=1: pcnt->prow) ----
__global__ void scan1_dual_kernel(const int* __restrict__ cnt, const int* __restrict__ pcnt,
                                  int* __restrict__ rowptr, int* __restrict__ prow,
                                  int* __restrict__ bs, float* __restrict__ dinv, int n) {
    const int* in = blockIdx.y ? pcnt : cnt;
    int* rp = blockIdx.y ? prow : rowptr;
    int* b = bs + blockIdx.y * 128;
    __shared__ int sh[1024];
    int tid = threadIdx.x;
    int i = blockIdx.x * 1024 + tid;
    int v = (i < n) ? in[i] : 0;
    if (blockIdx.y == 0 && i < n)
        dinv[i] = rsqrtf((float)(v + 1));      // +1 self-loop
    sh[tid] = v;
    __syncthreads();
    #pragma unroll
    for (int off = 1; off < 1024; off <<= 1) {
        int t = (tid >= off) ? sh[tid - off] : 0;
        __syncthreads();
        sh[tid] += t;
        __syncthreads();
    }
    if (i < n) rp[i] = sh[tid] - v;
    if (tid == 1023) b[blockIdx.x] = sh[1023];
}

__global__ void scan2_dual_kernel(int* bs, int nb, int* rowptr, int* prow, int n) {
    int a = threadIdx.x;
    if (a < 2) {
        int* b = bs + a * 128;
        int run = 0;
        for (int k = 0; k < nb; k++) { int t = b[k]; b[k] = run; run += t; }
        (a ? prow : rowptr)[n] = run;
    }
}

__global__ void scan3_dual_kernel(int* rowptr, int* prow, const int* __restrict__ bs, int n) {
    int* rp = blockIdx.y ? prow : rowptr;
    const int* b = bs + blockIdx.y * 128;
    int i = blockIdx.x * blockDim.x + threadIdx.x;
    if (i < n) rp[i] += b[i >> 10];
}

// ---------------- fused CSR scatter (edges + pool members) ----------------
__global__ void scatter_dual_kernel(const void* __restrict__ edge, long long ne,
                                    const void* __restrict__ dict, int n,
                                    const int* __restrict__ flag,
                                    const int* __restrict__ rowptr, int* __restrict__ fill,
                                    int* __restrict__ csrc, float* __restrict__ cnorm,
                                    const float* __restrict__ dinv,
                                    const int* __restrict__ prow, int* __restrict__ pfill,
                                    int* __restrict__ pnode, int nbE) {
    int is64 = flag[0];
    if ((int)blockIdx.x < nbE) {
        int e = blockIdx.x * blockDim.x + threadIdx.x;
        if (e < ne) {
            int s = idx_at(edge, e, is64);
            int d = idx_at(edge, ne + e, is64);
            int p = rowptr[d] + atomicAdd(&fill[d], 1);
            csrc[p] = s;
            cnorm[p] = dinv[s] * dinv[d];
        }
    } else {
        int v = (blockIdx.x - nbE) * blockDim.x + threadIdx.x;
        if (v < n) {
            int d = idx_at(dict, v, is64);
            int p = prow[d] + atomicAdd(&pfill[d], 1);
            pnode[p] = v;
        }
    }
}

// ---------------- tf32 tensor-core GEMM -> fp16 output ----------------
template <bool A_HALF>
__global__ void gemm_tf32_kernel(const void* __restrict__ Av, const float* __restrict__ W,
                                 __half* __restrict__ C, int n) {
    __shared__ __align__(16) float smemBuf[128 * 36 + 32 * 132];
    float (*As)[36]  = reinterpret_cast<float(*)[36]>(smemBuf);
    float (*Ws)[132] = reinterpret_cast<float(*)[132]>(smemBuf + 128 * 36);
    int tid = threadIdx.x;
    int warpId = tid >> 5;
    int wm = warpId & 3;
    int wn = warpId >> 2;
    int row0 = blockIdx.x * 128;

    wmma::fragment<wmma::accumulator, 16, 16, 8, float> acc[2][4];
    #pragma unroll
    for (int i = 0; i < 2; i++)
        #pragma unroll
        for (int j = 0; j < 4; j++) wmma::fill_fragment(acc[i][j], 0.0f);

    for (int kt = 0; kt < 128; kt += 32) {
        #pragma unroll
        for (int p = 0; p < 4; p++) {
            int i = tid + p * 256;
            int r = i >> 3;
            int c4 = (i & 7) * 4;
            int gr = row0 + r;
            float f0 = 0.f, f1 = 0.f, f2 = 0.f, f3 = 0.f;
            if (gr < n) {
                if (A_HALF) {
                    const __half* Ah = (const __half*)Av;
                    uint2 v = *reinterpret_cast<const uint2*>(Ah + (size_t)gr * 128 + kt + c4);
                    half2 h0 = *reinterpret_cast<half2*>(&v.x);
                    half2 h1 = *reinterpret_cast<half2*>(&v.y);
                    float2 a = __half22float2(h0), b = __half22float2(h1);
                    f0 = a.x; f1 = a.y; f2 = b.x; f3 = b.y;
                } else {
                    const float* Af = (const float*)Av;
                    float4 v = *reinterpret_cast<const float4*>(Af + (size_t)gr * 128 + kt + c4);
                    f0 = v.x; f1 = v.y; f2 = v.z; f3 = v.w;
                }
            }
            As[r][c4 + 0] = wmma::__float_to_tf32(f0);
            As[r][c4 + 1] = wmma::__float_to_tf32(f1);
            As[r][c4 + 2] = wmma::__float_to_tf32(f2);
            As[r][c4 + 3] = wmma::__float_to_tf32(f3);
        }
        #pragma unroll
        for (int p = 0; p < 4; p++) {
            int i = tid + p * 256;
            int r = i >> 5;
            int c4 = (i & 31) * 4;
            float4 v = *reinterpret_cast<const float4*>(W + (size_t)(kt + r) * 128 + c4);
            Ws[r][c4 + 0] = wmma::__float_to_tf32(v.x);
            Ws[r][c4 + 1] = wmma::__float_to_tf32(v.y);
            Ws[r][c4 + 2] = wmma::__float_to_tf32(v.z);
            Ws[r][c4 + 3] = wmma::__float_to_tf32(v.w);
        }
        __syncthreads();
        #pragma unroll
        for (int kk = 0; kk < 4; kk++) {
            wmma::fragment<wmma::matrix_a, 16, 16, 8, wmma::precision::tf32, wmma::row_major> af[2];
            wmma::fragment<wmma::matrix_b, 16, 16, 8, wmma::precision::tf32, wmma::row_major> bf[4];
            #pragma unroll
            for (int i = 0; i < 2; i++)
                wmma::load_matrix_sync(af[i], &As[wm * 32 + i * 16][kk * 8], 36);
            #pragma unroll
            for (int j = 0; j < 4; j++)
                wmma::load_matrix_sync(bf[j], &Ws[kk * 8][wn * 64 + j * 16], 132);
            #pragma unroll
            for (int i = 0; i < 2; i++)
                #pragma unroll
                for (int j = 0; j < 4; j++)
                    wmma::mma_sync(acc[i][j], af[i], bf[j], acc[i][j]);
        }
        __syncthreads();
    }
    // epilogue via smem -> fp16
    int er = tid >> 1;
    int ec0 = (tid & 1) * 32;
    #pragma unroll
    for (int p = 0; p < 2; p++) {
        if (wn == p) {
            #pragma unroll
            for (int i = 0; i < 2; i++)
                #pragma unroll
                for (int j = 0; j < 4; j++)
                    wmma::store_matrix_sync(&smemBuf[(wm * 32 + i * 16) * 64 + j * 16],
                                            acc[i][j], 64, wmma::mem_row_major);
        }
        __syncthreads();
        const float* src = smemBuf + er * 64 + ec0;
        __half* dst = C + (size_t)(row0 + er) * 128 + p * 64 + ec0;
        #pragma unroll
        for (int k = 0; k < 32; k += 2) {
            half2 h = __floats2half2_rn(src[k], src[k + 1]);
            *reinterpret_cast<half2*>(dst + k) = h;
        }
        __syncthreads();
    }
}

// ---------------- store helpers ----------------
__device__ __forceinline__ void store4(float* p, float a0, float a1, float a2, float a3) {
    *reinterpret_cast<float4*>(p) = make_float4(a0, a1, a2, a3);
}
__device__ __forceinline__ void store4(__half* p, float a0, float a1, float a2, float a3) {
    half2 h0 = __floats2half2_rn(a0, a1);
    half2 h1 = __floats2half2_rn(a2, a3);
    uint2 u;
    u.x = *reinterpret_cast<unsigned*>(&h0);
    u.y = *reinterpret_cast<unsigned*>(&h1);
    *reinterpret_cast<uint2*>(p) = u;
}
__device__ __forceinline__ void load4h(const __half* p, float& a0, float& a1, float& a2, float& a3) {
    uint2 v = *reinterpret_cast<const uint2*>(p);
    half2 h0 = *reinterpret_cast<half2*>(&v.x);
    half2 h1 = *reinterpret_cast<half2*>(&v.y);
    float2 f0 = __half22float2(h0), f1 = __half22float2(h1);
    a0 = f0.x; a1 = f0.y; a2 = f1.x; a3 = f1.y;
}

// ---------------- GCN aggregation: warp per dst node, lane = 4 features ----------------
template <typename OutT>
__global__ void agg_warp_kernel(const __half* __restrict__ xw, OutT* __restrict__ out,
                                const float* __restrict__ bias,
                                const int* __restrict__ rowptr, const int* __restrict__ csrc,
                                const float* __restrict__ cnorm, const float* __restrict__ dinv,
                                int n) {
    int w = (blockIdx.x * blockDim.x + threadIdx.x) >> 5;
    int lane = threadIdx.x & 31;
    if (w >= n) return;
    int beg = rowptr[w];
    int end = rowptr[w + 1];
    size_t loff = (size_t)lane * 4;
    float a0 = 0.f, a1 = 0.f, a2 = 0.f, a3 = 0.f;
    #pragma unroll 8
    for (int e = beg; e < end; e++) {
        int s = __ldg(csrc + e);
        float nm = __ldg(cnorm + e);
        float f0, f1, f2, f3;
        load4h(xw + (size_t)s * 128 + loff, f0, f1, f2, f3);
        a0 += f0 * nm; a1 += f1 * nm; a2 += f2 * nm; a3 += f3 * nm;
    }
    float di = dinv[w];
    float sw = di * di;
    {
        float f0, f1, f2, f3;
        load4h(xw + (size_t)w * 128 + loff, f0, f1, f2, f3);
        a0 += f0 * sw; a1 += f1 * sw; a2 += f2 * sw; a3 += f3 * sw;
    }
    float4 bb = *reinterpret_cast<const float4*>(bias + loff);
    a0 = fmaxf(a0 + bb.x, 0.f);
    a1 = fmaxf(a1 + bb.y, 0.f);
    a2 = fmaxf(a2 + bb.z, 0.f);
    a3 = fmaxf(a3 + bb.w, 0.f);
    store4(out + (size_t)w * 128 + loff, a0, a1, a2, a3);
}

// ---------------- mean-pool: warp per segment (fp16 in/out, fp32 accum) --------------
__global__ void pool_warp_kernel(const __half* __restrict__ h, __half* __restrict__ z,
                                 const int* __restrict__ prow, const int* __restrict__ pnode,
                                 int n) {
    int w = (blockIdx.x * blockDim.x + threadIdx.x) >> 5;
    int lane = threadIdx.x & 31;
    if (w >= n) return;
    int beg = prow[w];
    int end = prow[w + 1];
    size_t loff = (size_t)lane * 4;
    float a0 = 0.f, a1 = 0.f, a2 = 0.f, a3 = 0.f;
    for (int m = beg; m < end; m++) {
        int nd = __ldg(pnode + m);
        float f0, f1, f2, f3;
        load4h(h + (size_t)nd * 128 + loff, f0, f1, f2, f3);
        a0 += f0; a1 += f1; a2 += f2; a3 += f3;
    }
    float inv = 1.0f / fmaxf((float)(end - beg), 1.0f);
    store4(z + (size_t)w * 128 + loff, a0 * inv, a1 * inv, a2 * inv, a3 * inv);
}

// ---------------- decode: warp per edge, fp16 gather, fp32 dot ----------------
__global__ void decode_kernel(const __half* __restrict__ z,
                              const void* __restrict__ pos,
                              const void* __restrict__ neg,
                              const int* __restrict__ flag,
                              float* __restrict__ out, int ep) {
    int is64 = flag[0];
    int gw = (blockIdx.x * blockDim.x + threadIdx.x) >> 5;
    int lane = threadIdx.x & 31;
    int total = 2 * ep;
    if (gw >= total) return;
    int a, b;
    if (gw < ep) { a = idx_at(pos, gw, is64); b = idx_at(pos, (long long)ep + gw, is64); }
    else { int e = gw - ep; a = idx_at(neg, e, is64); b = idx_at(neg, (long long)ep + e, is64); }
    size_t loff = (size_t)lane * 4;
    float a0, a1, a2, a3, b0, b1, b2, b3;
    load4h(z + (size_t)a * 128 + loff, a0, a1, a2, a3);
    load4h(z + (size_t)b * 128 + loff, b0, b1, b2, b3);
    float s = a0 * b0 + a1 * b1 + a2 * b2 + a3 * b3;
    s += __shfl_xor_sync(0xffffffffu, s, 16);
    s += __shfl_xor_sync(0xffffffffu, s, 8);
    s += __shfl_xor_sync(0xffffffffu, s, 4);
    s += __shfl_xor_sync(0xffffffffu, s, 2);
    s += __shfl_xor_sync(0xffffffffu, s, 1);
    if (lane == 0) out[gw] = s;
}

// ---------------- launch ----------------
extern "C" void kernel_launch(void* const* d_in, const int* in_sizes, int n_in,
                              void* d_out, int out_size) {
    const float* x  = (const float*)d_in[0];
    const float* W1 = (const float*)d_in[1];
    const float* b1 = (const float*)d_in[2];
    const float* W2 = (const float*)d_in[3];
    const float* b2 = (const float*)d_in[4];
    const void*  edge = d_in[5];
    const void*  dict = d_in[6];
    const void*  pos  = d_in[7];
    const void*  neg  = d_in[8];
    float* out = (float*)d_out;

    const int n  = in_sizes[0] / HH;
    const int ne = in_sizes[5] / 2;
    const int ep = in_sizes[7] / 2;

    __half *xw, *h1, *h2, *z;
    float *dinv, *cnorm;
    int *cnt, *fill, *rowptr, *bsums, *csrc, *pcnt, *pfill, *prow, *pnode, *flag;
    cudaGetSymbolAddress((void**)&xw,    g_xw);
    cudaGetSymbolAddress((void**)&h1,    g_h1);
    cudaGetSymbolAddress((void**)&h2,    g_h2);
    cudaGetSymbolAddress((void**)&z,     g_z);
    cudaGetSymbolAddress((void**)&dinv,  g_dinv);
    cudaGetSymbolAddress((void**)&cnorm, g_cnorm);
    cudaGetSymbolAddress((void**)&cnt,   g_cnt);
    cudaGetSymbolAddress((void**)&fill,  g_fill);
    cudaGetSymbolAddress((void**)&rowptr,g_rowptr);
    cudaGetSymbolAddress((void**)&bsums, g_bsums);
    cudaGetSymbolAddress((void**)&csrc,  g_csrc);
    cudaGetSymbolAddress((void**)&pcnt,  g_pcnt);
    cudaGetSymbolAddress((void**)&pfill, g_pfill);
    cudaGetSymbolAddress((void**)&prow,  g_prow);
    cudaGetSymbolAddress((void**)&pnode, g_pnode);
    cudaGetSymbolAddress((void**)&flag,  g_is64);

    const int nb1024 = (n + 1023) / 1024;           // 98
    const int nbE = (ne + 255) / 256;               // 6250
    const int nbN = (n + 255) / 256;                // 391
    const int gemm_blocks = (n + 127) / 128;        // 782
    const int agg_blocks = (n + 7) / 8;

    // fork: GEMM1 (x @ W1) depends on nothing from preprocessing
    cudaEventRecord(g_evA, 0);
    cudaStreamWaitEvent(g_s1, g_evA, 0);
    gemm_tf32_kernel<false><<<gemm_blocks, 256, 0, g_s1>>>(x, W1, xw, n);
    cudaEventRecord(g_evB, g_s1);

    // preprocessing chain (default stream), fused
    zero_detect_kernel<<<nbN + 1, 256>>>(cnt, fill, pcnt, pfill, n, edge, flag);
    hist_dual_kernel<<<nbE + nbN, 256>>>(edge, (long long)ne, dict, n, flag, cnt, pcnt, nbE);
    {
        dim3 g1(nb1024, 2);
        scan1_dual_kernel<<<g1, 1024>>>(cnt, pcnt, rowptr, prow, bsums, dinv, n);
        scan2_dual_kernel<<<1, 32>>>(bsums, nb1024, rowptr, prow, n);
        dim3 g3(nbN, 2);
        scan3_dual_kernel<<<g3, 256>>>(rowptr, prow, bsums, n);
    }
    scatter_dual_kernel<<<nbE + nbN, 256>>>(edge, (long long)ne, dict, n, flag,
                                            rowptr, fill, csrc, cnorm, dinv,
                                            prow, pfill, pnode, nbE);

    // join: agg1 needs CSR + GEMM1 output
    cudaStreamWaitEvent(0, g_evB, 0);
    agg_warp_kernel<__half><<<agg_blocks, 256>>>(xw, h1, b1, rowptr, csrc, cnorm, dinv, n);
    // layer 2
    gemm_tf32_kernel<true><<<gemm_blocks, 256>>>(h1, W2, xw, n);
    agg_warp_kernel<__half><<<agg_blocks, 256>>>(xw, h2, b2, rowptr, csrc, cnorm, dinv, n);
    // mean pool (fp16)
    pool_warp_kernel<<<agg_blocks, 256>>>(h2, z, prow, pnode, n);
    // decode
    int total_warps = 2 * ep;
    int dec_blocks = (total_warps * 32 + 255) / 256;
    decode_kernel<<<dec_blocks, 256>>>(z, pos, neg, flag, out, ep);
}

// round 6
// speedup vs baseline: 1.7825x; 1.1220x over previous
#include <cuda_runtime.h>
#include <cuda_fp16.h>
#include <mma.h>
#include <cstdint>
#include <cstddef>

using namespace nvcuda;

#define NN 100000
#define NN_PAD 100096           // multiple of 128 for tail-free GEMM stores
#define HH 128
#define EE 1600000
#define EPP 200000

// ---------------- scratch (device globals; no allocation allowed) ----------------
__device__ __half g_xw[(size_t)NN_PAD * HH];   // x @ W1 (fp16)
__device__ __half g_h1[(size_t)NN_PAD * HH];   // relu(agg(xw)) @ W2 (fp16)
__device__ __half g_h2[(size_t)NN * HH];       // layer-2 activations (fp16)
__device__ __half g_z[(size_t)NN * HH];        // pooled embeddings (fp16)
__device__ float  g_dinv[NN];
__device__ int2   g_epair[EE];                 // {src, bitcast(norm)} interleaved CSR
__device__ int    g_cnt[NN];
__device__ int    g_fill[NN];
__device__ int    g_rowptr[NN + 1];
__device__ int    g_bsums[2 * 128];
__device__ int    g_pcnt[NN];
__device__ int    g_pfill[NN];
__device__ int    g_prow[NN + 1];
__device__ int    g_pnode[NN];
__device__ int    g_is64[1];

// ---------------- streams/events for graph fork-join (created pre-main) ----------
static cudaStream_t g_s1 = nullptr;
static cudaEvent_t  g_evA = nullptr, g_evB = nullptr;
static const bool g_init = []() {
    cudaStreamCreateWithFlags(&g_s1, cudaStreamNonBlocking);
    cudaEventCreateWithFlags(&g_evA, cudaEventDisableTiming);
    cudaEventCreateWithFlags(&g_evB, cudaEventDisableTiming);
    return true;
}();

// ---------------- index accessor ----------------
__device__ __forceinline__ int idx_at(const void* __restrict__ p, long long i, int is64) {
    if (is64) return (int)((const long long*)p)[i];
    return ((const int*)p)[i];
}

// ---------------- fused: zero counters + detect index dtype ----------------
__global__ void zero_detect_kernel(int* cnt, int* fill, int* pcnt, int* pfill, int n,
                                   const void* __restrict__ p, int* __restrict__ flag) {
    if (blockIdx.x == gridDim.x - 1) {
        const int2* q = (const int2*)p;
        __shared__ int any_hi;
        if (threadIdx.x == 0) any_hi = 0;
        __syncthreads();
        for (int i = threadIdx.x; i < 1024; i += blockDim.x)
            if (q[i].y != 0) any_hi = 1;
        __syncthreads();
        if (threadIdx.x == 0) flag[0] = any_hi ? 0 : 1;
        return;
    }
    int i = blockIdx.x * blockDim.x + threadIdx.x;
    if (i < n) { cnt[i] = 0; fill[i] = 0; pcnt[i] = 0; pfill[i] = 0; }
}

// ---------------- fused histograms ----------------
__global__ void hist_dual_kernel(const void* __restrict__ edge, long long ne,
                                 const void* __restrict__ dict, int n,
                                 const int* __restrict__ flag,
                                 int* __restrict__ cnt, int* __restrict__ pcnt, int nbE) {
    int is64 = flag[0];
    if ((int)blockIdx.x < nbE) {
        int i = blockIdx.x * blockDim.x + threadIdx.x;
        if (i < ne) atomicAdd(&cnt[idx_at(edge, ne + i, is64)], 1);
    } else {
        int i = (blockIdx.x - nbE) * blockDim.x + threadIdx.x;
        if (i < n) atomicAdd(&pcnt[idx_at(dict, i, is64)], 1);
    }
}

// ---------------- dual exclusive scan ----------------
__global__ void scan1_dual_kernel(const int* __restrict__ cnt, const int* __restrict__ pcnt,
                                  int* __restrict__ rowptr, int* __restrict__ prow,
                                  int* __restrict__ bs, float* __restrict__ dinv, int n) {
    const int* in = blockIdx.y ? pcnt : cnt;
    int* rp = blockIdx.y ? prow : rowptr;
    int* b = bs + blockIdx.y * 128;
    __shared__ int sh[1024];
    int tid = threadIdx.x;
    int i = blockIdx.x * 1024 + tid;
    int v = (i < n) ? in[i] : 0;
    if (blockIdx.y == 0 && i < n)
        dinv[i] = rsqrtf((float)(v + 1));
    sh[tid] = v;
    __syncthreads();
    #pragma unroll
    for (int off = 1; off < 1024; off <<= 1) {
        int t = (tid >= off) ? sh[tid - off] : 0;
        __syncthreads();
        sh[tid] += t;
        __syncthreads();
    }
    if (i < n) rp[i] = sh[tid] - v;
    if (tid == 1023) b[blockIdx.x] = sh[1023];
}

__global__ void scan2_dual_kernel(int* bs, int nb, int* rowptr, int* prow, int n) {
    int a = threadIdx.x;
    if (a < 2) {
        int* b = bs + a * 128;
        int run = 0;
        for (int k = 0; k < nb; k++) { int t = b[k]; b[k] = run; run += t; }
        (a ? prow : rowptr)[n] = run;
    }
}

__global__ void scan3_dual_kernel(int* rowptr, int* prow, const int* __restrict__ bs, int n) {
    int* rp = blockIdx.y ? prow : rowptr;
    const int* b = bs + blockIdx.y * 128;
    int i = blockIdx.x * blockDim.x + threadIdx.x;
    if (i < n) rp[i] += b[i >> 10];
}

// ---------------- fused CSR scatter (edges interleaved + pool members) ----------------
__global__ void scatter_dual_kernel(const void* __restrict__ edge, long long ne,
                                    const void* __restrict__ dict, int n,
                                    const int* __restrict__ flag,
                                    const int* __restrict__ rowptr, int* __restrict__ fill,
                                    int2* __restrict__ epair,
                                    const float* __restrict__ dinv,
                                    const int* __restrict__ prow, int* __restrict__ pfill,
                                    int* __restrict__ pnode, int nbE) {
    int is64 = flag[0];
    if ((int)blockIdx.x < nbE) {
        int e = blockIdx.x * blockDim.x + threadIdx.x;
        if (e < ne) {
            int s = idx_at(edge, e, is64);
            int d = idx_at(edge, ne + e, is64);
            int p = rowptr[d] + atomicAdd(&fill[d], 1);
            float nm = dinv[s] * dinv[d];
            epair[p] = make_int2(s, __float_as_int(nm));
        }
    } else {
        int v = (blockIdx.x - nbE) * blockDim.x + threadIdx.x;
        if (v < n) {
            int d = idx_at(dict, v, is64);
            int p = prow[d] + atomicAdd(&pfill[d], 1);
            pnode[p] = v;
        }
    }
}

// ---------------- helpers ----------------
__device__ __forceinline__ void load4h(const __half* p, float& a0, float& a1, float& a2, float& a3) {
    uint2 v = *reinterpret_cast<const uint2*>(p);
    half2 h0 = *reinterpret_cast<half2*>(&v.x);
    half2 h1 = *reinterpret_cast<half2*>(&v.y);
    float2 f0 = __half22float2(h0), f1 = __half22float2(h1);
    a0 = f0.x; a1 = f0.y; a2 = f1.x; a3 = f1.y;
}
__device__ __forceinline__ void store4h(__half* p, float a0, float a1, float a2, float a3) {
    half2 h0 = __floats2half2_rn(a0, a1);
    half2 h1 = __floats2half2_rn(a2, a3);
    uint2 u;
    u.x = *reinterpret_cast<unsigned*>(&h0);
    u.y = *reinterpret_cast<unsigned*>(&h1);
    *reinterpret_cast<uint2*>(p) = u;
}

// ---------------- shared GEMM phase-2 (fp16 HMMA, As fully staged in smem) --------
// As: [128][136] fp16 (full K), Ws: [32][136] fp16 chunk. C: fp16 [NN_PAD,128].
#define AS_STRIDE 136
__device__ __forceinline__ void gemm_phase2(__half (*As)[AS_STRIDE], __half (*Ws)[AS_STRIDE],
                                            float* ebuf, const float* __restrict__ W,
                                            __half* __restrict__ C, int row0, int tid) {
    int warpId = tid >> 5;
    int wm = warpId & 3;
    int wn = warpId >> 2;
    wmma::fragment<wmma::accumulator, 16, 16, 16, float> acc[2][4];
    #pragma unroll
    for (int i = 0; i < 2; i++)
        #pragma unroll
        for (int j = 0; j < 4; j++) wmma::fill_fragment(acc[i][j], 0.0f);

    for (int kt2 = 0; kt2 < 128; kt2 += 32) {
        // stage W chunk 32x128 fp32 -> fp16
        #pragma unroll
        for (int p = 0; p < 4; p++) {
            int idx = tid + p * 256;
            int r = idx >> 5;
            int c4 = (idx & 31) * 4;
            float4 v = *reinterpret_cast<const float4*>(W + (size_t)(kt2 + r) * 128 + c4);
            *reinterpret_cast<half2*>(&Ws[r][c4])     = __floats2half2_rn(v.x, v.y);
            *reinterpret_cast<half2*>(&Ws[r][c4 + 2]) = __floats2half2_rn(v.z, v.w);
        }
        __syncthreads();
        #pragma unroll
        for (int kk = 0; kk < 2; kk++) {
            int k0 = kt2 + kk * 16;
            wmma::fragment<wmma::matrix_a, 16, 16, 16, __half, wmma::row_major> af[2];
            wmma::fragment<wmma::matrix_b, 16, 16, 16, __half, wmma::row_major> bf[4];
            #pragma unroll
            for (int i = 0; i < 2; i++)
                wmma::load_matrix_sync(af[i], &As[wm * 32 + i * 16][k0], AS_STRIDE);
            #pragma unroll
            for (int j = 0; j < 4; j++)
                wmma::load_matrix_sync(bf[j], &Ws[kk * 16][wn * 64 + j * 16], AS_STRIDE);
            #pragma unroll
            for (int i = 0; i < 2; i++)
                #pragma unroll
                for (int j = 0; j < 4; j++)
                    wmma::mma_sync(acc[i][j], af[i], bf[j], acc[i][j]);
        }
        __syncthreads();
    }
    // epilogue via smem (ebuf aliases As) -> fp16 global
    int er = tid >> 1;
    int ec0 = (tid & 1) * 32;
    #pragma unroll
    for (int p = 0; p < 2; p++) {
        if (wn == p) {
            #pragma unroll
            for (int i = 0; i < 2; i++)
                #pragma unroll
                for (int j = 0; j < 4; j++)
                    wmma::store_matrix_sync(&ebuf[(wm * 32 + i * 16) * 64 + j * 16],
                                            acc[i][j], 64, wmma::mem_row_major);
        }
        __syncthreads();
        const float* src = ebuf + er * 64 + ec0;
        __half* dst = C + (size_t)(row0 + er) * 128 + p * 64 + ec0;
        #pragma unroll
        for (int k = 0; k < 32; k += 2)
            *reinterpret_cast<half2*>(dst + k) = __floats2half2_rn(src[k], src[k + 1]);
        __syncthreads();
    }
}

#define SMEM_BYTES (128 * AS_STRIDE * 2 + 32 * AS_STRIDE * 2)

// ---------------- GEMM1: C = toH16(A_fp32) @ W (fp16 HMMA) ----------------
__global__ void gemm16_kernel(const float* __restrict__ A, const float* __restrict__ W,
                              __half* __restrict__ C, int n) {
    __shared__ __align__(16) unsigned char smemRaw[SMEM_BYTES];
    __half (*As)[AS_STRIDE] = reinterpret_cast<__half(*)[AS_STRIDE]>(smemRaw);
    __half (*Ws)[AS_STRIDE] = reinterpret_cast<__half(*)[AS_STRIDE]>(smemRaw + 128 * AS_STRIDE * 2);
    float* ebuf = reinterpret_cast<float*>(smemRaw);
    int tid = threadIdx.x;
    int row0 = blockIdx.x * 128;
    // stage full A tile 128x128 fp32 -> fp16 (zero rows >= n)
    #pragma unroll
    for (int p = 0; p < 16; p++) {
        int idx = tid + p * 256;          // 0..4095 float4 slots
        int r = idx >> 5;
        int c4 = (idx & 31) * 4;
        int gr = row0 + r;
        float4 v = make_float4(0.f, 0.f, 0.f, 0.f);
        if (gr < n) v = *reinterpret_cast<const float4*>(A + (size_t)gr * 128 + c4);
        *reinterpret_cast<half2*>(&As[r][c4])     = __floats2half2_rn(v.x, v.y);
        *reinterpret_cast<half2*>(&As[r][c4 + 2]) = __floats2half2_rn(v.z, v.w);
    }
    __syncthreads();
    gemm_phase2(As, Ws, ebuf, W, C, row0, tid);
}

// ---------------- FUSED: h1tile = relu(agg(xw)+b1); C = h1tile @ W2 ----------------
__global__ void agg_gemm_fused_kernel(const __half* __restrict__ xw,
                                      const float* __restrict__ b1,
                                      const float* __restrict__ W2,
                                      __half* __restrict__ C,
                                      const int* __restrict__ rowptr,
                                      const int2* __restrict__ epair,
                                      const float* __restrict__ dinv, int n) {
    __shared__ __align__(16) unsigned char smemRaw[SMEM_BYTES];
    __half (*As)[AS_STRIDE] = reinterpret_cast<__half(*)[AS_STRIDE]>(smemRaw);
    __half (*Ws)[AS_STRIDE] = reinterpret_cast<__half(*)[AS_STRIDE]>(smemRaw + 128 * AS_STRIDE * 2);
    float* ebuf = reinterpret_cast<float*>(smemRaw);
    int tid = threadIdx.x;
    int warpId = tid >> 5;
    int lane = tid & 31;
    int row0 = blockIdx.x * 128;
    size_t loff = (size_t)lane * 4;
    float4 bb = *reinterpret_cast<const float4*>(b1 + loff);

    // phase 1: aggregate this block's 128 node-rows into As (fp16)
    #pragma unroll 1
    for (int it = 0; it < 16; it++) {
        int lr = warpId + it * 8;          // local row 0..127
        int v = row0 + lr;
        float a0 = 0.f, a1 = 0.f, a2 = 0.f, a3 = 0.f;
        if (v < n) {
            int beg = rowptr[v];
            int end = rowptr[v + 1];
            #pragma unroll 8
            for (int e = beg; e < end; e++) {
                int2 pr = __ldg(epair + e);
                float nm = __int_as_float(pr.y);
                float f0, f1, f2, f3;
                load4h(xw + (size_t)pr.x * 128 + loff, f0, f1, f2, f3);
                a0 += f0 * nm; a1 += f1 * nm; a2 += f2 * nm; a3 += f3 * nm;
            }
            float di = dinv[v];
            float sw = di * di;
            float f0, f1, f2, f3;
            load4h(xw + (size_t)v * 128 + loff, f0, f1, f2, f3);
            a0 = fmaxf(a0 + f0 * sw + bb.x, 0.f);
            a1 = fmaxf(a1 + f1 * sw + bb.y, 0.f);
            a2 = fmaxf(a2 + f2 * sw + bb.z, 0.f);
            a3 = fmaxf(a3 + f3 * sw + bb.w, 0.f);
        }
        *reinterpret_cast<half2*>(&As[lr][lane * 4])     = __floats2half2_rn(a0, a1);
        *reinterpret_cast<half2*>(&As[lr][lane * 4 + 2]) = __floats2half2_rn(a2, a3);
    }
    __syncthreads();
    // phase 2: GEMM vs W2
    gemm_phase2(As, Ws, ebuf, W2, C, row0, tid);
}

// ---------------- layer-2 aggregation: warp per dst node ----------------
__global__ void agg_warp_kernel(const __half* __restrict__ xw, __half* __restrict__ out,
                                const float* __restrict__ bias,
                                const int* __restrict__ rowptr, const int2* __restrict__ epair,
                                const float* __restrict__ dinv, int n) {
    int w = (blockIdx.x * blockDim.x + threadIdx.x) >> 5;
    int lane = threadIdx.x & 31;
    if (w >= n) return;
    int beg = rowptr[w];
    int end = rowptr[w + 1];
    size_t loff = (size_t)lane * 4;
    float a0 = 0.f, a1 = 0.f, a2 = 0.f, a3 = 0.f;
    #pragma unroll 8
    for (int e = beg; e < end; e++) {
        int2 pr = __ldg(epair + e);
        float nm = __int_as_float(pr.y);
        float f0, f1, f2, f3;
        load4h(xw + (size_t)pr.x * 128 + loff, f0, f1, f2, f3);
        a0 += f0 * nm; a1 += f1 * nm; a2 += f2 * nm; a3 += f3 * nm;
    }
    float di = dinv[w];
    float sw = di * di;
    {
        float f0, f1, f2, f3;
        load4h(xw + (size_t)w * 128 + loff, f0, f1, f2, f3);
        a0 += f0 * sw; a1 += f1 * sw; a2 += f2 * sw; a3 += f3 * sw;
    }
    float4 bbv = *reinterpret_cast<const float4*>(bias + loff);
    store4h(out + (size_t)w * 128 + loff,
            fmaxf(a0 + bbv.x, 0.f), fmaxf(a1 + bbv.y, 0.f),
            fmaxf(a2 + bbv.z, 0.f), fmaxf(a3 + bbv.w, 0.f));
}

// ---------------- mean-pool: warp per segment ----------------
__global__ void pool_warp_kernel(const __half* __restrict__ h, __half* __restrict__ z,
                                 const int* __restrict__ prow, const int* __restrict__ pnode,
                                 int n) {
    int w = (blockIdx.x * blockDim.x + threadIdx.x) >> 5;
    int lane = threadIdx.x & 31;
    if (w >= n) return;
    int beg = prow[w];
    int end = prow[w + 1];
    size_t loff = (size_t)lane * 4;
    float a0 = 0.f, a1 = 0.f, a2 = 0.f, a3 = 0.f;
    for (int m = beg; m < end; m++) {
        int nd = __ldg(pnode + m);
        float f0, f1, f2, f3;
        load4h(h + (size_t)nd * 128 + loff, f0, f1, f2, f3);
        a0 += f0; a1 += f1; a2 += f2; a3 += f3;
    }
    float inv = 1.0f / fmaxf((float)(end - beg), 1.0f);
    store4h(z + (size_t)w * 128 + loff, a0 * inv, a1 * inv, a2 * inv, a3 * inv);
}

// ---------------- decode: warp per edge ----------------
__global__ void decode_kernel(const __half* __restrict__ z,
                              const void* __restrict__ pos,
                              const void* __restrict__ neg,
                              const int* __restrict__ flag,
                              float* __restrict__ out, int ep) {
    int is64 = flag[0];
    int gw = (blockIdx.x * blockDim.x + threadIdx.x) >> 5;
    int lane = threadIdx.x & 31;
    int total = 2 * ep;
    if (gw >= total) return;
    int a, b;
    if (gw < ep) { a = idx_at(pos, gw, is64); b = idx_at(pos, (long long)ep + gw, is64); }
    else { int e = gw - ep; a = idx_at(neg, e, is64); b = idx_at(neg, (long long)ep + e, is64); }
    size_t loff = (size_t)lane * 4;
    float a0, a1, a2, a3, b0, b1, b2, b3;
    load4h(z + (size_t)a * 128 + loff, a0, a1, a2, a3);
    load4h(z + (size_t)b * 128 + loff, b0, b1, b2, b3);
    float s = a0 * b0 + a1 * b1 + a2 * b2 + a3 * b3;
    s += __shfl_xor_sync(0xffffffffu, s, 16);
    s += __shfl_xor_sync(0xffffffffu, s, 8);
    s += __shfl_xor_sync(0xffffffffu, s, 4);
    s += __shfl_xor_sync(0xffffffffu, s, 2);
    s += __shfl_xor_sync(0xffffffffu, s, 1);
    if (lane == 0) out[gw] = s;
}

// ---------------- launch ----------------
extern "C" void kernel_launch(void* const* d_in, const int* in_sizes, int n_in,
                              void* d_out, int out_size) {
    const float* x  = (const float*)d_in[0];
    const float* W1 = (const float*)d_in[1];
    const float* b1 = (const float*)d_in[2];
    const float* W2 = (const float*)d_in[3];
    const float* b2 = (const float*)d_in[4];
    const void*  edge = d_in[5];
    const void*  dict = d_in[6];
    const void*  pos  = d_in[7];
    const void*  neg  = d_in[8];
    float* out = (float*)d_out;

    const int n  = in_sizes[0] / HH;
    const int ne = in_sizes[5] / 2;
    const int ep = in_sizes[7] / 2;

    __half *xw, *h1, *h2, *z;
    float *dinv;
    int2* epair;
    int *cnt, *fill, *rowptr, *bsums, *pcnt, *pfill, *prow, *pnode, *flag;
    cudaGetSymbolAddress((void**)&xw,    g_xw);
    cudaGetSymbolAddress((void**)&h1,    g_h1);
    cudaGetSymbolAddress((void**)&h2,    g_h2);
    cudaGetSymbolAddress((void**)&z,     g_z);
    cudaGetSymbolAddress((void**)&dinv,  g_dinv);
    cudaGetSymbolAddress((void**)&epair, g_epair);
    cudaGetSymbolAddress((void**)&cnt,   g_cnt);
    cudaGetSymbolAddress((void**)&fill,  g_fill);
    cudaGetSymbolAddress((void**)&rowptr,g_rowptr);
    cudaGetSymbolAddress((void**)&bsums, g_bsums);
    cudaGetSymbolAddress((void**)&pcnt,  g_pcnt);
    cudaGetSymbolAddress((void**)&pfill, g_pfill);
    cudaGetSymbolAddress((void**)&prow,  g_prow);
    cudaGetSymbolAddress((void**)&pnode, g_pnode);
    cudaGetSymbolAddress((void**)&flag,  g_is64);

    const int nb1024 = (n + 1023) / 1024;
    const int nbE = (ne + 255) / 256;
    const int nbN = (n + 255) / 256;
    const int gemm_blocks = (n + 127) / 128;
    const int agg_blocks = (n + 7) / 8;

    // fork: GEMM1 depends only on x, W1
    cudaEventRecord(g_evA, 0);
    cudaStreamWaitEvent(g_s1, g_evA, 0);
    gemm16_kernel<<<gemm_blocks, 256, 0, g_s1>>>(x, W1, xw, n);
    cudaEventRecord(g_evB, g_s1);

    // preprocessing chain (default stream)
    zero_detect_kernel<<<nbN + 1, 256>>>(cnt, fill, pcnt, pfill, n, edge, flag);
    hist_dual_kernel<<<nbE + nbN, 256>>>(edge, (long long)ne, dict, n, flag, cnt, pcnt, nbE);
    {
        dim3 g1(nb1024, 2);
        scan1_dual_kernel<<<g1, 1024>>>(cnt, pcnt, rowptr, prow, bsums, dinv, n);
        scan2_dual_kernel<<<1, 32>>>(bsums, nb1024, rowptr, prow, n);
        dim3 g3(nbN, 2);
        scan3_dual_kernel<<<g3, 256>>>(rowptr, prow, bsums, n);
    }
    scatter_dual_kernel<<<nbE + nbN, 256>>>(edge, (long long)ne, dict, n, flag,
                                            rowptr, fill, epair, dinv,
                                            prow, pfill, pnode, nbE);

    // join: fused agg1 + GEMM2 (needs CSR + xw)
    cudaStreamWaitEvent(0, g_evB, 0);
    agg_gemm_fused_kernel<<<gemm_blocks, 256>>>(xw, b1, W2, h1, rowptr, epair, dinv, n);
    // layer-2 aggregation
    agg_warp_kernel<<<agg_blocks, 256>>>(h1, h2, b2, rowptr, epair, dinv, n);
    // mean pool
    pool_warp_kernel<<<agg_blocks, 256>>>(h2, z, prow, pnode, n);
    // decode
    int total_warps = 2 * ep;
    int dec_blocks = (total_warps * 32 + 255) / 256;
    decode_kernel<<<dec_blocks, 256>>>(z, pos, neg, flag, out, ep);
}

// round 7
// speedup vs baseline: 1.8288x; 1.0260x over previous
#include <cuda_runtime.h>
#include <cuda_fp16.h>
#include <mma.h>
#include <cstdint>
#include <cstddef>

using namespace nvcuda;

#define NN 100000
#define NN_PAD 100096
#define HH 128
#define EE 1600000
#define EPP 200000

// ---------------- scratch ----------------
__device__ __half g_xw[(size_t)NN_PAD * HH];
__device__ __half g_h1[(size_t)NN_PAD * HH];
__device__ __half g_h2[(size_t)NN * HH];
__device__ __half g_z[(size_t)NN * HH];
__device__ float  g_dinv[NN];
__device__ int2   g_epair[EE];
__device__ int    g_cnt[NN];
__device__ int    g_fill[NN];
__device__ int    g_rowptr[NN + 1];
__device__ int    g_bsums[2 * 128];
__device__ int    g_pcnt[NN];
__device__ int    g_pfill[NN];
__device__ int    g_prow[NN + 1];
__device__ int    g_pnode[NN];
__device__ int    g_is64[1];

// ---------------- streams/events (created pre-main) ----------
static cudaStream_t g_s1 = nullptr;
static cudaEvent_t  g_evA = nullptr, g_evB = nullptr;
static const bool g_init = []() {
    cudaStreamCreateWithFlags(&g_s1, cudaStreamNonBlocking);
    cudaEventCreateWithFlags(&g_evA, cudaEventDisableTiming);
    cudaEventCreateWithFlags(&g_evB, cudaEventDisableTiming);
    return true;
}();

__device__ __forceinline__ int idx_at(const void* __restrict__ p, long long i, int is64) {
    if (is64) return (int)((const long long*)p)[i];
    return ((const int*)p)[i];
}

// ---------------- fused: zero counters + detect index dtype ----------------
__global__ void zero_detect_kernel(int* cnt, int* fill, int* pcnt, int* pfill, int n,
                                   const void* __restrict__ p, int* __restrict__ flag) {
    if (blockIdx.x == gridDim.x - 1) {
        const int2* q = (const int2*)p;
        __shared__ int any_hi;
        if (threadIdx.x == 0) any_hi = 0;
        __syncthreads();
        for (int i = threadIdx.x; i < 1024; i += blockDim.x)
            if (q[i].y != 0) any_hi = 1;
        __syncthreads();
        if (threadIdx.x == 0) flag[0] = any_hi ? 0 : 1;
        return;
    }
    int i = blockIdx.x * blockDim.x + threadIdx.x;
    if (i < n) { cnt[i] = 0; fill[i] = 0; pcnt[i] = 0; pfill[i] = 0; }
}

// ---------------- fused histograms ----------------
__global__ void hist_dual_kernel(const void* __restrict__ edge, long long ne,
                                 const void* __restrict__ dict, int n,
                                 const int* __restrict__ flag,
                                 int* __restrict__ cnt, int* __restrict__ pcnt, int nbE) {
    int is64 = flag[0];
    if ((int)blockIdx.x < nbE) {
        int i = blockIdx.x * blockDim.x + threadIdx.x;
        if (i < ne) atomicAdd(&cnt[idx_at(edge, ne + i, is64)], 1);
    } else {
        int i = (blockIdx.x - nbE) * blockDim.x + threadIdx.x;
        if (i < n) atomicAdd(&pcnt[idx_at(dict, i, is64)], 1);
    }
}

// ---------------- dual exclusive scan ----------------
__global__ void scan1_dual_kernel(const int* __restrict__ cnt, const int* __restrict__ pcnt,
                                  int* __restrict__ rowptr, int* __restrict__ prow,
                                  int* __restrict__ bs, float* __restrict__ dinv, int n) {
    const int* in = blockIdx.y ? pcnt : cnt;
    int* rp = blockIdx.y ? prow : rowptr;
    int* b = bs + blockIdx.y * 128;
    __shared__ int sh[1024];
    int tid = threadIdx.x;
    int i = blockIdx.x * 1024 + tid;
    int v = (i < n) ? in[i] : 0;
    if (blockIdx.y == 0 && i < n)
        dinv[i] = rsqrtf((float)(v + 1));
    sh[tid] = v;
    __syncthreads();
    #pragma unroll
    for (int off = 1; off < 1024; off <<= 1) {
        int t = (tid >= off) ? sh[tid - off] : 0;
        __syncthreads();
        sh[tid] += t;
        __syncthreads();
    }
    if (i < n) rp[i] = sh[tid] - v;
    if (tid == 1023) b[blockIdx.x] = sh[1023];
}

__global__ void scan2_dual_kernel(int* bs, int nb, int* rowptr, int* prow, int n) {
    int a = threadIdx.x;
    if (a < 2) {
        int* b = bs + a * 128;
        int run = 0;
        for (int k = 0; k < nb; k++) { int t = b[k]; b[k] = run; run += t; }
        (a ? prow : rowptr)[n] = run;
    }
}

__global__ void scan3_dual_kernel(int* rowptr, int* prow, const int* __restrict__ bs, int n) {
    int* rp = blockIdx.y ? prow : rowptr;
    const int* b = bs + blockIdx.y * 128;
    int i = blockIdx.x * blockDim.x + threadIdx.x;
    if (i < n) rp[i] += b[i >> 10];
}

// ---------------- fused CSR scatter ----------------
__global__ void scatter_dual_kernel(const void* __restrict__ edge, long long ne,
                                    const void* __restrict__ dict, int n,
                                    const int* __restrict__ flag,
                                    const int* __restrict__ rowptr, int* __restrict__ fill,
                                    int2* __restrict__ epair,
                                    const float* __restrict__ dinv,
                                    const int* __restrict__ prow, int* __restrict__ pfill,
                                    int* __restrict__ pnode, int nbE) {
    int is64 = flag[0];
    if ((int)blockIdx.x < nbE) {
        int e = blockIdx.x * blockDim.x + threadIdx.x;
        if (e < ne) {
            int s = idx_at(edge, e, is64);
            int d = idx_at(edge, ne + e, is64);
            int p = rowptr[d] + atomicAdd(&fill[d], 1);
            float nm = dinv[s] * dinv[d];
            epair[p] = make_int2(s, __float_as_int(nm));
        }
    } else {
        int v = (blockIdx.x - nbE) * blockDim.x + threadIdx.x;
        if (v < n) {
            int d = idx_at(dict, v, is64);
            int p = prow[d] + atomicAdd(&pfill[d], 1);
            pnode[p] = v;
        }
    }
}

// ---------------- helpers ----------------
__device__ __forceinline__ void load4h(const __half* p, float& a0, float& a1, float& a2, float& a3) {
    uint2 v = *reinterpret_cast<const uint2*>(p);
    half2 h0 = *reinterpret_cast<half2*>(&v.x);
    half2 h1 = *reinterpret_cast<half2*>(&v.y);
    float2 f0 = __half22float2(h0), f1 = __half22float2(h1);
    a0 = f0.x; a1 = f0.y; a2 = f1.x; a3 = f1.y;
}
__device__ __forceinline__ void store4h(__half* p, float a0, float a1, float a2, float a3) {
    half2 h0 = __floats2half2_rn(a0, a1);
    half2 h1 = __floats2half2_rn(a2, a3);
    uint2 u;
    u.x = *reinterpret_cast<unsigned*>(&h0);
    u.y = *reinterpret_cast<unsigned*>(&h1);
    *reinterpret_cast<uint2*>(p) = u;
}

// Dual-node edge accumulation: two independent chains for MLP.
// acc[0..3] node A, acc[4..7] node B.
__device__ __forceinline__ void agg_pair(const __half* __restrict__ xw, size_t loff,
                                         const int2* __restrict__ epair,
                                         int e0, int end0, int e1, int end1,
                                         float* acc) {
    // interleaved main loop (2 chains), 4x unrolled
    while (e0 + 4 <= end0 && e1 + 4 <= end1) {
        #pragma unroll
        for (int u = 0; u < 4; u++) {
            int2 p0 = __ldg(epair + e0 + u);
            int2 p1 = __ldg(epair + e1 + u);
            float x0, x1, x2, x3, y0, y1, y2, y3;
            load4h(xw + (size_t)p0.x * 128 + loff, x0, x1, x2, x3);
            load4h(xw + (size_t)p1.x * 128 + loff, y0, y1, y2, y3);
            float n0 = __int_as_float(p0.y), n1 = __int_as_float(p1.y);
            acc[0] += x0 * n0; acc[1] += x1 * n0; acc[2] += x2 * n0; acc[3] += x3 * n0;
            acc[4] += y0 * n1; acc[5] += y1 * n1; acc[6] += y2 * n1; acc[7] += y3 * n1;
        }
        e0 += 4; e1 += 4;
    }
    while (e0 < end0 && e1 < end1) {
        int2 p0 = __ldg(epair + e0);
        int2 p1 = __ldg(epair + e1);
        float x0, x1, x2, x3, y0, y1, y2, y3;
        load4h(xw + (size_t)p0.x * 128 + loff, x0, x1, x2, x3);
        load4h(xw + (size_t)p1.x * 128 + loff, y0, y1, y2, y3);
        float n0 = __int_as_float(p0.y), n1 = __int_as_float(p1.y);
        acc[0] += x0 * n0; acc[1] += x1 * n0; acc[2] += x2 * n0; acc[3] += x3 * n0;
        acc[4] += y0 * n1; acc[5] += y1 * n1; acc[6] += y2 * n1; acc[7] += y3 * n1;
        e0++; e1++;
    }
    #pragma unroll 4
    for (; e0 < end0; e0++) {
        int2 p0 = __ldg(epair + e0);
        float x0, x1, x2, x3;
        load4h(xw + (size_t)p0.x * 128 + loff, x0, x1, x2, x3);
        float n0 = __int_as_float(p0.y);
        acc[0] += x0 * n0; acc[1] += x1 * n0; acc[2] += x2 * n0; acc[3] += x3 * n0;
    }
    #pragma unroll 4
    for (; e1 < end1; e1++) {
        int2 p1 = __ldg(epair + e1);
        float y0, y1, y2, y3;
        load4h(xw + (size_t)p1.x * 128 + loff, y0, y1, y2, y3);
        float n1 = __int_as_float(p1.y);
        acc[4] += y0 * n1; acc[5] += y1 * n1; acc[6] += y2 * n1; acc[7] += y3 * n1;
    }
}

// ---------------- shared GEMM phase-2 (fp16 HMMA) --------
#define AS_STRIDE 136
__device__ __forceinline__ void gemm_phase2(__half (*As)[AS_STRIDE], __half (*Ws)[AS_STRIDE],
                                            float* ebuf, const float* __restrict__ W,
                                            __half* __restrict__ C, int row0, int tid) {
    int warpId = tid >> 5;
    int wm = warpId & 3;
    int wn = warpId >> 2;
    wmma::fragment<wmma::accumulator, 16, 16, 16, float> acc[2][4];
    #pragma unroll
    for (int i = 0; i < 2; i++)
        #pragma unroll
        for (int j = 0; j < 4; j++) wmma::fill_fragment(acc[i][j], 0.0f);

    for (int kt2 = 0; kt2 < 128; kt2 += 32) {
        #pragma unroll
        for (int p = 0; p < 4; p++) {
            int idx = tid + p * 256;
            int r = idx >> 5;
            int c4 = (idx & 31) * 4;
            float4 v = *reinterpret_cast<const float4*>(W + (size_t)(kt2 + r) * 128 + c4);
            *reinterpret_cast<half2*>(&Ws[r][c4])     = __floats2half2_rn(v.x, v.y);
            *reinterpret_cast<half2*>(&Ws[r][c4 + 2]) = __floats2half2_rn(v.z, v.w);
        }
        __syncthreads();
        #pragma unroll
        for (int kk = 0; kk < 2; kk++) {
            int k0 = kt2 + kk * 16;
            wmma::fragment<wmma::matrix_a, 16, 16, 16, __half, wmma::row_major> af[2];
            wmma::fragment<wmma::matrix_b, 16, 16, 16, __half, wmma::row_major> bf[4];
            #pragma unroll
            for (int i = 0; i < 2; i++)
                wmma::load_matrix_sync(af[i], &As[wm * 32 + i * 16][k0], AS_STRIDE);
            #pragma unroll
            for (int j = 0; j < 4; j++)
                wmma::load_matrix_sync(bf[j], &Ws[kk * 16][wn * 64 + j * 16], AS_STRIDE);
            #pragma unroll
            for (int i = 0; i < 2; i++)
                #pragma unroll
                for (int j = 0; j < 4; j++)
                    wmma::mma_sync(acc[i][j], af[i], bf[j], acc[i][j]);
        }
        __syncthreads();
    }
    int er = tid >> 1;
    int ec0 = (tid & 1) * 32;
    #pragma unroll
    for (int p = 0; p < 2; p++) {
        if (wn == p) {
            #pragma unroll
            for (int i = 0; i < 2; i++)
                #pragma unroll
                for (int j = 0; j < 4; j++)
                    wmma::store_matrix_sync(&ebuf[(wm * 32 + i * 16) * 64 + j * 16],
                                            acc[i][j], 64, wmma::mem_row_major);
        }
        __syncthreads();
        const float* src = ebuf + er * 64 + ec0;
        __half* dst = C + (size_t)(row0 + er) * 128 + p * 64 + ec0;
        #pragma unroll
        for (int k = 0; k < 32; k += 2)
            *reinterpret_cast<half2*>(dst + k) = __floats2half2_rn(src[k], src[k + 1]);
        __syncthreads();
    }
}

#define SMEM_BYTES (128 * AS_STRIDE * 2 + 32 * AS_STRIDE * 2)

// ---------------- GEMM1: C = toH16(A_fp32) @ W ----------------
__global__ void gemm16_kernel(const float* __restrict__ A, const float* __restrict__ W,
                              __half* __restrict__ C, int n) {
    __shared__ __align__(16) unsigned char smemRaw[SMEM_BYTES];
    __half (*As)[AS_STRIDE] = reinterpret_cast<__half(*)[AS_STRIDE]>(smemRaw);
    __half (*Ws)[AS_STRIDE] = reinterpret_cast<__half(*)[AS_STRIDE]>(smemRaw + 128 * AS_STRIDE * 2);
    float* ebuf = reinterpret_cast<float*>(smemRaw);
    int tid = threadIdx.x;
    int row0 = blockIdx.x * 128;
    #pragma unroll
    for (int p = 0; p < 16; p++) {
        int idx = tid + p * 256;
        int r = idx >> 5;
        int c4 = (idx & 31) * 4;
        int gr = row0 + r;
        float4 v = make_float4(0.f, 0.f, 0.f, 0.f);
        if (gr < n) v = *reinterpret_cast<const float4*>(A + (size_t)gr * 128 + c4);
        *reinterpret_cast<half2*>(&As[r][c4])     = __floats2half2_rn(v.x, v.y);
        *reinterpret_cast<half2*>(&As[r][c4 + 2]) = __floats2half2_rn(v.z, v.w);
    }
    __syncthreads();
    gemm_phase2(As, Ws, ebuf, W, C, row0, tid);
}

// ---------------- FUSED: h1tile = relu(agg(xw)+b1); C = h1tile @ W2 ----------------
__global__ __launch_bounds__(256)
void agg_gemm_fused_kernel(const __half* __restrict__ xw,
                           const float* __restrict__ b1,
                           const float* __restrict__ W2,
                           __half* __restrict__ C,
                           const int* __restrict__ rowptr,
                           const int2* __restrict__ epair,
                           const float* __restrict__ dinv, int n) {
    __shared__ __align__(16) unsigned char smemRaw[SMEM_BYTES];
    __half (*As)[AS_STRIDE] = reinterpret_cast<__half(*)[AS_STRIDE]>(smemRaw);
    __half (*Ws)[AS_STRIDE] = reinterpret_cast<__half(*)[AS_STRIDE]>(smemRaw + 128 * AS_STRIDE * 2);
    float* ebuf = reinterpret_cast<float*>(smemRaw);
    int tid = threadIdx.x;
    int warpId = tid >> 5;
    int lane = tid & 31;
    int row0 = blockIdx.x * 128;
    size_t loff = (size_t)lane * 4;
    float4 bb = *reinterpret_cast<const float4*>(b1 + loff);

    // phase 1: aggregate 128 rows; each warp does 8 row-PAIRS (dual chains)
    #pragma unroll 1
    for (int it = 0; it < 8; it++) {
        int lr0 = warpId + it * 16;        // rows 0..7,16..23,...
        int lr1 = lr0 + 8;                 // rows 8..15,24..31,...
        int v0 = row0 + lr0;
        int v1 = row0 + lr1;
        float acc[8] = {0.f, 0.f, 0.f, 0.f, 0.f, 0.f, 0.f, 0.f};
        int e0 = 0, end0 = 0, e1 = 0, end1 = 0;
        if (v0 < n) { e0 = rowptr[v0]; end0 = rowptr[v0 + 1]; }
        if (v1 < n) { e1 = rowptr[v1]; end1 = rowptr[v1 + 1]; }
        agg_pair(xw, loff, epair, e0, end0, e1, end1, acc);
        if (v0 < n) {
            float di = dinv[v0]; float sw = di * di;
            float f0, f1, f2, f3;
            load4h(xw + (size_t)v0 * 128 + loff, f0, f1, f2, f3);
            acc[0] = fmaxf(acc[0] + f0 * sw + bb.x, 0.f);
            acc[1] = fmaxf(acc[1] + f1 * sw + bb.y, 0.f);
            acc[2] = fmaxf(acc[2] + f2 * sw + bb.z, 0.f);
            acc[3] = fmaxf(acc[3] + f3 * sw + bb.w, 0.f);
        } else { acc[0] = acc[1] = acc[2] = acc[3] = 0.f; }
        if (v1 < n) {
            float di = dinv[v1]; float sw = di * di;
            float f0, f1, f2, f3;
            load4h(xw + (size_t)v1 * 128 + loff, f0, f1, f2, f3);
            acc[4] = fmaxf(acc[4] + f0 * sw + bb.x, 0.f);
            acc[5] = fmaxf(acc[5] + f1 * sw + bb.y, 0.f);
            acc[6] = fmaxf(acc[6] + f2 * sw + bb.z, 0.f);
            acc[7] = fmaxf(acc[7] + f3 * sw + bb.w, 0.f);
        } else { acc[4] = acc[5] = acc[6] = acc[7] = 0.f; }
        *reinterpret_cast<half2*>(&As[lr0][lane * 4])     = __floats2half2_rn(acc[0], acc[1]);
        *reinterpret_cast<half2*>(&As[lr0][lane * 4 + 2]) = __floats2half2_rn(acc[2], acc[3]);
        *reinterpret_cast<half2*>(&As[lr1][lane * 4])     = __floats2half2_rn(acc[4], acc[5]);
        *reinterpret_cast<half2*>(&As[lr1][lane * 4 + 2]) = __floats2half2_rn(acc[6], acc[7]);
    }
    __syncthreads();
    gemm_phase2(As, Ws, ebuf, W2, C, row0, tid);
}

// ---------------- layer-2 aggregation: warp per TWO dst nodes ----------------
__global__ __launch_bounds__(256)
void agg_warp2_kernel(const __half* __restrict__ xw, __half* __restrict__ out,
                      const float* __restrict__ bias,
                      const int* __restrict__ rowptr, const int2* __restrict__ epair,
                      const float* __restrict__ dinv, int n) {
    int w = (blockIdx.x * blockDim.x + threadIdx.x) >> 5;
    int lane = threadIdx.x & 31;
    int v0 = 2 * w;
    int v1 = 2 * w + 1;
    if (v0 >= n) return;
    size_t loff = (size_t)lane * 4;
    float acc[8] = {0.f, 0.f, 0.f, 0.f, 0.f, 0.f, 0.f, 0.f};
    int e0 = rowptr[v0], end0 = rowptr[v0 + 1];
    int e1 = 0, end1 = 0;
    if (v1 < n) { e1 = rowptr[v1]; end1 = rowptr[v1 + 1]; }
    agg_pair(xw, loff, epair, e0, end0, e1, end1, acc);
    float4 bbv = *reinterpret_cast<const float4*>(bias + loff);
    {
        float di = dinv[v0]; float sw = di * di;
        float f0, f1, f2, f3;
        load4h(xw + (size_t)v0 * 128 + loff, f0, f1, f2, f3);
        store4h(out + (size_t)v0 * 128 + loff,
                fmaxf(acc[0] + f0 * sw + bbv.x, 0.f), fmaxf(acc[1] + f1 * sw + bbv.y, 0.f),
                fmaxf(acc[2] + f2 * sw + bbv.z, 0.f), fmaxf(acc[3] + f3 * sw + bbv.w, 0.f));
    }
    if (v1 < n) {
        float di = dinv[v1]; float sw = di * di;
        float f0, f1, f2, f3;
        load4h(xw + (size_t)v1 * 128 + loff, f0, f1, f2, f3);
        store4h(out + (size_t)v1 * 128 + loff,
                fmaxf(acc[4] + f0 * sw + bbv.x, 0.f), fmaxf(acc[5] + f1 * sw + bbv.y, 0.f),
                fmaxf(acc[6] + f2 * sw + bbv.z, 0.f), fmaxf(acc[7] + f3 * sw + bbv.w, 0.f));
    }
}

// ---------------- mean-pool: warp per segment ----------------
__global__ void pool_warp_kernel(const __half* __restrict__ h, __half* __restrict__ z,
                                 const int* __restrict__ prow, const int* __restrict__ pnode,
                                 int n) {
    int w = (blockIdx.x * blockDim.x + threadIdx.x) >> 5;
    int lane = threadIdx.x & 31;
    if (w >= n) return;
    int beg = prow[w];
    int end = prow[w + 1];
    size_t loff = (size_t)lane * 4;
    float a0 = 0.f, a1 = 0.f, a2 = 0.f, a3 = 0.f;
    #pragma unroll 4
    for (int m = beg; m < end; m++) {
        int nd = __ldg(pnode + m);
        float f0, f1, f2, f3;
        load4h(h + (size_t)nd * 128 + loff, f0, f1, f2, f3);
        a0 += f0; a1 += f1; a2 += f2; a3 += f3;
    }
    float inv = 1.0f / fmaxf((float)(end - beg), 1.0f);
    store4h(z + (size_t)w * 128 + loff, a0 * inv, a1 * inv, a2 * inv, a3 * inv);
}

// ---------------- decode: warp per edge ----------------
__global__ void decode_kernel(const __half* __restrict__ z,
                              const void* __restrict__ pos,
                              const void* __restrict__ neg,
                              const int* __restrict__ flag,
                              float* __restrict__ out, int ep) {
    int is64 = flag[0];
    int gw = (blockIdx.x * blockDim.x + threadIdx.x) >> 5;
    int lane = threadIdx.x & 31;
    int total = 2 * ep;
    if (gw >= total) return;
    int a, b;
    if (gw < ep) { a = idx_at(pos, gw, is64); b = idx_at(pos, (long long)ep + gw, is64); }
    else { int e = gw - ep; a = idx_at(neg, e, is64); b = idx_at(neg, (long long)ep + e, is64); }
    size_t loff = (size_t)lane * 4;
    float a0, a1, a2, a3, b0, b1, b2, b3;
    load4h(z + (size_t)a * 128 + loff, a0, a1, a2, a3);
    load4h(z + (size_t)b * 128 + loff, b0, b1, b2, b3);
    float s = a0 * b0 + a1 * b1 + a2 * b2 + a3 * b3;
    s += __shfl_xor_sync(0xffffffffu, s, 16);
    s += __shfl_xor_sync(0xffffffffu, s, 8);
    s += __shfl_xor_sync(0xffffffffu, s, 4);
    s += __shfl_xor_sync(0xffffffffu, s, 2);
    s += __shfl_xor_sync(0xffffffffu, s, 1);
    if (lane == 0) out[gw] = s;
}

// ---------------- launch ----------------
extern "C" void kernel_launch(void* const* d_in, const int* in_sizes, int n_in,
                              void* d_out, int out_size) {
    const float* x  = (const float*)d_in[0];
    const float* W1 = (const float*)d_in[1];
    const float* b1 = (const float*)d_in[2];
    const float* W2 = (const float*)d_in[3];
    const float* b2 = (const float*)d_in[4];
    const void*  edge = d_in[5];
    const void*  dict = d_in[6];
    const void*  pos  = d_in[7];
    const void*  neg  = d_in[8];
    float* out = (float*)d_out;

    const int n  = in_sizes[0] / HH;
    const int ne = in_sizes[5] / 2;
    const int ep = in_sizes[7] / 2;

    __half *xw, *h1, *h2, *z;
    float *dinv;
    int2* epair;
    int *cnt, *fill, *rowptr, *bsums, *pcnt, *pfill, *prow, *pnode, *flag;
    cudaGetSymbolAddress((void**)&xw,    g_xw);
    cudaGetSymbolAddress((void**)&h1,    g_h1);
    cudaGetSymbolAddress((void**)&h2,    g_h2);
    cudaGetSymbolAddress((void**)&z,     g_z);
    cudaGetSymbolAddress((void**)&dinv,  g_dinv);
    cudaGetSymbolAddress((void**)&epair, g_epair);
    cudaGetSymbolAddress((void**)&cnt,   g_cnt);
    cudaGetSymbolAddress((void**)&fill,  g_fill);
    cudaGetSymbolAddress((void**)&rowptr,g_rowptr);
    cudaGetSymbolAddress((void**)&bsums, g_bsums);
    cudaGetSymbolAddress((void**)&pcnt,  g_pcnt);
    cudaGetSymbolAddress((void**)&pfill, g_pfill);
    cudaGetSymbolAddress((void**)&prow,  g_prow);
    cudaGetSymbolAddress((void**)&pnode, g_pnode);
    cudaGetSymbolAddress((void**)&flag,  g_is64);

    const int nb1024 = (n + 1023) / 1024;
    const int nbE = (ne + 255) / 256;
    const int nbN = (n + 255) / 256;
    const int gemm_blocks = (n + 127) / 128;
    const int aggw2_blocks = ((n + 1) / 2 + 7) / 8;   // warp per 2 nodes, 8 warps/block
    const int poolw_blocks = (n + 7) / 8;

    // fork: GEMM1 depends only on x, W1
    cudaEventRecord(g_evA, 0);
    cudaStreamWaitEvent(g_s1, g_evA, 0);
    gemm16_kernel<<<gemm_blocks, 256, 0, g_s1>>>(x, W1, xw, n);
    cudaEventRecord(g_evB, g_s1);

    // preprocessing chain (default stream)
    zero_detect_kernel<<<nbN + 1, 256>>>(cnt, fill, pcnt, pfill, n, edge, flag);
    hist_dual_kernel<<<nbE + nbN, 256>>>(edge, (long long)ne, dict, n, flag, cnt, pcnt, nbE);
    {
        dim3 g1(nb1024, 2);
        scan1_dual_kernel<<<g1, 1024>>>(cnt, pcnt, rowptr, prow, bsums, dinv, n);
        scan2_dual_kernel<<<1, 32>>>(bsums, nb1024, rowptr, prow, n);
        dim3 g3(nbN, 2);
        scan3_dual_kernel<<<g3, 256>>>(rowptr, prow, bsums, n);
    }
    scatter_dual_kernel<<<nbE + nbN, 256>>>(edge, (long long)ne, dict, n, flag,
                                            rowptr, fill, epair, dinv,
                                            prow, pfill, pnode, nbE);

    // join: fused agg1 + GEMM2
    cudaStreamWaitEvent(0, g_evB, 0);
    agg_gemm_fused_kernel<<<gemm_blocks, 256>>>(xw, b1, W2, h1, rowptr, epair, dinv, n);
    // layer-2 aggregation (dual-node warps)
    agg_warp2_kernel<<<aggw2_blocks, 256>>>(h1, h2, b2, rowptr, epair, dinv, n);
    // mean pool
    pool_warp_kernel<<<poolw_blocks, 256>>>(h2, z, prow, pnode, n);
    // decode
    int total_warps = 2 * ep;
    int dec_blocks = (total_warps * 32 + 255) / 256;
    decode_kernel<<<dec_blocks, 256>>>(z, pos, neg, flag, out, ep);
}

// round 8
// speedup vs baseline: 2.0610x; 1.1270x over previous
#include <cuda_runtime.h>
#include <cuda_fp16.h>
#include <mma.h>
#include <cstdint>
#include <cstddef>

using namespace nvcuda;

#define NN 100000
#define NN_PAD 100096
#define HH 128
#define EE 1600000
#define EPP 200000

// ---------------- scratch ----------------
__device__ __half g_xw[(size_t)NN_PAD * HH];
__device__ __half g_h1[(size_t)NN_PAD * HH];
__device__ __half g_h2[(size_t)NN * HH];
__device__ __half g_z[(size_t)NN * HH];
__device__ float  g_dinv[NN];
__device__ int2   g_epair[EE];
__device__ int    g_cnt[NN];
__device__ int    g_fill[NN];
__device__ int    g_rowptr[NN + 1];
__device__ int    g_sflag[256];               // lookback flags (2 x 128)
__device__ int    g_pcnt[NN];
__device__ int    g_pfill[NN];
__device__ int    g_prow[NN + 1];
__device__ int    g_pnode[NN];
__device__ int    g_is64[1];

// ---------------- streams/events (created pre-main) ----------
static cudaStream_t g_s1 = nullptr;
static cudaEvent_t  g_evA = nullptr, g_evB = nullptr;
static const bool g_init = []() {
    cudaStreamCreateWithFlags(&g_s1, cudaStreamNonBlocking);
    cudaEventCreateWithFlags(&g_evA, cudaEventDisableTiming);
    cudaEventCreateWithFlags(&g_evB, cudaEventDisableTiming);
    return true;
}();

__device__ __forceinline__ int idx_at(const void* __restrict__ p, long long i, int is64) {
    if (is64) return (int)((const long long*)p)[i];
    return ((const int*)p)[i];
}

// ---------------- fused: zero counters + flags + detect index dtype ----------------
__global__ void zero_detect_kernel(int* cnt, int* fill, int* pcnt, int* pfill, int n,
                                   const void* __restrict__ p, int* __restrict__ flag,
                                   int* __restrict__ sflag) {
    if (blockIdx.x == gridDim.x - 1) {
        const int2* q = (const int2*)p;
        __shared__ int any_hi;
        if (threadIdx.x == 0) any_hi = 0;
        __syncthreads();
        for (int i = threadIdx.x; i < 1024; i += blockDim.x)
            if (q[i].y != 0) any_hi = 1;
        __syncthreads();
        if (threadIdx.x == 0) flag[0] = any_hi ? 0 : 1;
        return;
    }
    if (blockIdx.x == 0) sflag[threadIdx.x] = 0;   // 256 flags
    int i = blockIdx.x * blockDim.x + threadIdx.x;
    if (i < n) { cnt[i] = 0; fill[i] = 0; pcnt[i] = 0; pfill[i] = 0; }
}

// ---------------- fused histograms ----------------
__global__ void hist_dual_kernel(const void* __restrict__ edge, long long ne,
                                 const void* __restrict__ dict, int n,
                                 const int* __restrict__ flag,
                                 int* __restrict__ cnt, int* __restrict__ pcnt, int nbE) {
    int is64 = flag[0];
    if ((int)blockIdx.x < nbE) {
        int i = blockIdx.x * blockDim.x + threadIdx.x;
        if (i < ne) atomicAdd(&cnt[idx_at(edge, ne + i, is64)], 1);
    } else {
        int i = (blockIdx.x - nbE) * blockDim.x + threadIdx.x;
        if (i < n) atomicAdd(&pcnt[idx_at(dict, i, is64)], 1);
    }
}

// ---------------- single-pass dual exclusive scan (decoupled lookback) ----------------
// grid (nb, 2): y=0: cnt->rowptr (+dinv), y=1: pcnt->prow. flag slot = aggregate+1.
__global__ void scan_onepass_kernel(const int* __restrict__ cnt, const int* __restrict__ pcnt,
                                    int* __restrict__ rowptr, int* __restrict__ prow,
                                    float* __restrict__ dinv, int* __restrict__ sflag,
                                    int n, int nb) {
    int y = blockIdx.y;
    const int* in = y ? pcnt : cnt;
    int* rp = y ? prow : rowptr;
    int* fl = sflag + y * 128;
    __shared__ int sh[1024];
    __shared__ int sprefix;
    int tid = threadIdx.x;
    int b = blockIdx.x;
    int i = b * 1024 + tid;
    int v = (i < n) ? in[i] : 0;
    if (y == 0 && i < n)
        dinv[i] = rsqrtf((float)(v + 1));   // +1 self-loop
    sh[tid] = v;
    if (tid == 0) sprefix = 0;
    __syncthreads();
    #pragma unroll
    for (int off = 1; off < 1024; off <<= 1) {
        int t = (tid >= off) ? sh[tid - off] : 0;
        __syncthreads();
        sh[tid] += t;
        __syncthreads();
    }
    int total = sh[1023];
    if (tid == 0) atomicExch(&fl[b], total + 1);   // publish aggregate (L2-strong)
    // lookback: sum all predecessor aggregates
    if (tid < b) {
        int f;
        do { f = *((volatile int*)&fl[tid]); } while (f == 0);
        atomicAdd(&sprefix, f - 1);
    }
    __syncthreads();
    int pre = sprefix;
    if (i < n) rp[i] = pre + sh[tid] - v;          // exclusive + cross-block prefix
    if (b == nb - 1 && tid == 1023) rp[n] = pre + total;
}

// ---------------- fused CSR scatter ----------------
__global__ void scatter_dual_kernel(const void* __restrict__ edge, long long ne,
                                    const void* __restrict__ dict, int n,
                                    const int* __restrict__ flag,
                                    const int* __restrict__ rowptr, int* __restrict__ fill,
                                    int2* __restrict__ epair,
                                    const float* __restrict__ dinv,
                                    const int* __restrict__ prow, int* __restrict__ pfill,
                                    int* __restrict__ pnode, int nbE) {
    int is64 = flag[0];
    if ((int)blockIdx.x < nbE) {
        int e = blockIdx.x * blockDim.x + threadIdx.x;
        if (e < ne) {
            int s = idx_at(edge, e, is64);
            int d = idx_at(edge, ne + e, is64);
            int p = rowptr[d] + atomicAdd(&fill[d], 1);
            float nm = dinv[s] * dinv[d];
            epair[p] = make_int2(s, __float_as_int(nm));
        }
    } else {
        int v = (blockIdx.x - nbE) * blockDim.x + threadIdx.x;
        if (v < n) {
            int d = idx_at(dict, v, is64);
            int p = prow[d] + atomicAdd(&pfill[d], 1);
            pnode[p] = v;
        }
    }
}

// ---------------- helpers ----------------
__device__ __forceinline__ void load4h(const __half* p, float& a0, float& a1, float& a2, float& a3) {
    uint2 v = *reinterpret_cast<const uint2*>(p);
    half2 h0 = *reinterpret_cast<half2*>(&v.x);
    half2 h1 = *reinterpret_cast<half2*>(&v.y);
    float2 f0 = __half22float2(h0), f1 = __half22float2(h1);
    a0 = f0.x; a1 = f0.y; a2 = f1.x; a3 = f1.y;
}
__device__ __forceinline__ void store4h(__half* p, float a0, float a1, float a2, float a3) {
    half2 h0 = __floats2half2_rn(a0, a1);
    half2 h1 = __floats2half2_rn(a2, a3);
    uint2 u;
    u.x = *reinterpret_cast<unsigned*>(&h0);
    u.y = *reinterpret_cast<unsigned*>(&h1);
    *reinterpret_cast<uint2*>(p) = u;
}

// Dual-node edge accumulation (two independent chains).
__device__ __forceinline__ void agg_pair(const __half* __restrict__ xw, size_t loff,
                                         const int2* __restrict__ epair,
                                         int e0, int end0, int e1, int end1,
                                         float* acc) {
    while (e0 + 4 <= end0 && e1 + 4 <= end1) {
        #pragma unroll
        for (int u = 0; u < 4; u++) {
            int2 p0 = __ldg(epair + e0 + u);
            int2 p1 = __ldg(epair + e1 + u);
            float x0, x1, x2, x3, y0, y1, y2, y3;
            load4h(xw + (size_t)p0.x * 128 + loff, x0, x1, x2, x3);
            load4h(xw + (size_t)p1.x * 128 + loff, y0, y1, y2, y3);
            float n0 = __int_as_float(p0.y), n1 = __int_as_float(p1.y);
            acc[0] += x0 * n0; acc[1] += x1 * n0; acc[2] += x2 * n0; acc[3] += x3 * n0;
            acc[4] += y0 * n1; acc[5] += y1 * n1; acc[6] += y2 * n1; acc[7] += y3 * n1;
        }
        e0 += 4; e1 += 4;
    }
    while (e0 < end0 && e1 < end1) {
        int2 p0 = __ldg(epair + e0);
        int2 p1 = __ldg(epair + e1);
        float x0, x1, x2, x3, y0, y1, y2, y3;
        load4h(xw + (size_t)p0.x * 128 + loff, x0, x1, x2, x3);
        load4h(xw + (size_t)p1.x * 128 + loff, y0, y1, y2, y3);
        float n0 = __int_as_float(p0.y), n1 = __int_as_float(p1.y);
        acc[0] += x0 * n0; acc[1] += x1 * n0; acc[2] += x2 * n0; acc[3] += x3 * n0;
        acc[4] += y0 * n1; acc[5] += y1 * n1; acc[6] += y2 * n1; acc[7] += y3 * n1;
        e0++; e1++;
    }
    #pragma unroll 4
    for (; e0 < end0; e0++) {
        int2 p0 = __ldg(epair + e0);
        float x0, x1, x2, x3;
        load4h(xw + (size_t)p0.x * 128 + loff, x0, x1, x2, x3);
        float n0 = __int_as_float(p0.y);
        acc[0] += x0 * n0; acc[1] += x1 * n0; acc[2] += x2 * n0; acc[3] += x3 * n0;
    }
    #pragma unroll 4
    for (; e1 < end1; e1++) {
        int2 p1 = __ldg(epair + e1);
        float y0, y1, y2, y3;
        load4h(xw + (size_t)p1.x * 128 + loff, y0, y1, y2, y3);
        float n1 = __int_as_float(p1.y);
        acc[4] += y0 * n1; acc[5] += y1 * n1; acc[6] += y2 * n1; acc[7] += y3 * n1;
    }
}

#define AS_STRIDE 136
#define SMEM_BYTES (128 * AS_STRIDE * 2 + 32 * AS_STRIDE * 2)

// ---------------- GEMM phase-2, 256-thread variant (8 warps, 32x64 warp tile) ------
__device__ __forceinline__ void gemm_phase2_256(__half (*As)[AS_STRIDE], __half (*Ws)[AS_STRIDE],
                                                float* ebuf, const float* __restrict__ W,
                                                __half* __restrict__ C, int row0, int tid) {
    int warpId = tid >> 5;
    int wm = warpId & 3;
    int wn = warpId >> 2;
    wmma::fragment<wmma::accumulator, 16, 16, 16, float> acc[2][4];
    #pragma unroll
    for (int i = 0; i < 2; i++)
        #pragma unroll
        for (int j = 0; j < 4; j++) wmma::fill_fragment(acc[i][j], 0.0f);

    for (int kt2 = 0; kt2 < 128; kt2 += 32) {
        #pragma unroll
        for (int p = 0; p < 4; p++) {
            int idx = tid + p * 256;
            int r = idx >> 5;
            int c4 = (idx & 31) * 4;
            float4 v = *reinterpret_cast<const float4*>(W + (size_t)(kt2 + r) * 128 + c4);
            *reinterpret_cast<half2*>(&Ws[r][c4])     = __floats2half2_rn(v.x, v.y);
            *reinterpret_cast<half2*>(&Ws[r][c4 + 2]) = __floats2half2_rn(v.z, v.w);
        }
        __syncthreads();
        #pragma unroll
        for (int kk = 0; kk < 2; kk++) {
            int k0 = kt2 + kk * 16;
            wmma::fragment<wmma::matrix_a, 16, 16, 16, __half, wmma::row_major> af[2];
            wmma::fragment<wmma::matrix_b, 16, 16, 16, __half, wmma::row_major> bf[4];
            #pragma unroll
            for (int i = 0; i < 2; i++)
                wmma::load_matrix_sync(af[i], &As[wm * 32 + i * 16][k0], AS_STRIDE);
            #pragma unroll
            for (int j = 0; j < 4; j++)
                wmma::load_matrix_sync(bf[j], &Ws[kk * 16][wn * 64 + j * 16], AS_STRIDE);
            #pragma unroll
            for (int i = 0; i < 2; i++)
                #pragma unroll
                for (int j = 0; j < 4; j++)
                    wmma::mma_sync(acc[i][j], af[i], bf[j], acc[i][j]);
        }
        __syncthreads();
    }
    int er = tid >> 1;
    int ec0 = (tid & 1) * 32;
    #pragma unroll
    for (int p = 0; p < 2; p++) {
        if (wn == p) {
            #pragma unroll
            for (int i = 0; i < 2; i++)
                #pragma unroll
                for (int j = 0; j < 4; j++)
                    wmma::store_matrix_sync(&ebuf[(wm * 32 + i * 16) * 64 + j * 16],
                                            acc[i][j], 64, wmma::mem_row_major);
        }
        __syncthreads();
        const float* src = ebuf + er * 64 + ec0;
        __half* dst = C + (size_t)(row0 + er) * 128 + p * 64 + ec0;
        #pragma unroll
        for (int k = 0; k < 32; k += 2)
            *reinterpret_cast<half2*>(dst + k) = __floats2half2_rn(src[k], src[k + 1]);
        __syncthreads();
    }
}

// ---------------- GEMM1: 256 threads (overlapped with prep) ----------------
__global__ void gemm16_kernel(const float* __restrict__ A, const float* __restrict__ W,
                              __half* __restrict__ C, int n) {
    __shared__ __align__(16) unsigned char smemRaw[SMEM_BYTES];
    __half (*As)[AS_STRIDE] = reinterpret_cast<__half(*)[AS_STRIDE]>(smemRaw);
    __half (*Ws)[AS_STRIDE] = reinterpret_cast<__half(*)[AS_STRIDE]>(smemRaw + 128 * AS_STRIDE * 2);
    float* ebuf = reinterpret_cast<float*>(smemRaw);
    int tid = threadIdx.x;
    int row0 = blockIdx.x * 128;
    #pragma unroll
    for (int p = 0; p < 16; p++) {
        int idx = tid + p * 256;
        int r = idx >> 5;
        int c4 = (idx & 31) * 4;
        int gr = row0 + r;
        float4 v = make_float4(0.f, 0.f, 0.f, 0.f);
        if (gr < n) v = *reinterpret_cast<const float4*>(A + (size_t)gr * 128 + c4);
        *reinterpret_cast<half2*>(&As[r][c4])     = __floats2half2_rn(v.x, v.y);
        *reinterpret_cast<half2*>(&As[r][c4 + 2]) = __floats2half2_rn(v.z, v.w);
    }
    __syncthreads();
    gemm_phase2_256(As, Ws, ebuf, W, C, row0, tid);
}

// ---------------- FUSED (512 threads): h1tile = relu(agg(xw)+b1); C = h1tile @ W2 ----
__global__ __launch_bounds__(512)
void agg_gemm_fused_kernel(const __half* __restrict__ xw,
                           const float* __restrict__ b1,
                           const float* __restrict__ W2,
                           __half* __restrict__ C,
                           const int* __restrict__ rowptr,
                           const int2* __restrict__ epair,
                           const float* __restrict__ dinv, int n) {
    __shared__ __align__(16) unsigned char smemRaw[SMEM_BYTES];
    __half (*As)[AS_STRIDE] = reinterpret_cast<__half(*)[AS_STRIDE]>(smemRaw);
    __half (*Ws)[AS_STRIDE] = reinterpret_cast<__half(*)[AS_STRIDE]>(smemRaw + 128 * AS_STRIDE * 2);
    float* ebuf = reinterpret_cast<float*>(smemRaw);
    int tid = threadIdx.x;
    int warpId = tid >> 5;            // 0..15
    int lane = tid & 31;
    int row0 = blockIdx.x * 128;
    size_t loff = (size_t)lane * 4;
    float4 bb = *reinterpret_cast<const float4*>(b1 + loff);

    // phase 1: 16 warps x 4 row-pairs (dual chains)
    #pragma unroll 1
    for (int it = 0; it < 4; it++) {
        int lr0 = warpId + it * 32;    // 0..15, 32..47, 64..79, 96..111
        int lr1 = lr0 + 16;
        int v0 = row0 + lr0;
        int v1 = row0 + lr1;
        float acc[8] = {0.f, 0.f, 0.f, 0.f, 0.f, 0.f, 0.f, 0.f};
        int e0 = 0, end0 = 0, e1 = 0, end1 = 0;
        if (v0 < n) { e0 = rowptr[v0]; end0 = rowptr[v0 + 1]; }
        if (v1 < n) { e1 = rowptr[v1]; end1 = rowptr[v1 + 1]; }
        agg_pair(xw, loff, epair, e0, end0, e1, end1, acc);
        if (v0 < n) {
            float di = dinv[v0]; float sw = di * di;
            float f0, f1, f2, f3;
            load4h(xw + (size_t)v0 * 128 + loff, f0, f1, f2, f3);
            acc[0] = fmaxf(acc[0] + f0 * sw + bb.x, 0.f);
            acc[1] = fmaxf(acc[1] + f1 * sw + bb.y, 0.f);
            acc[2] = fmaxf(acc[2] + f2 * sw + bb.z, 0.f);
            acc[3] = fmaxf(acc[3] + f3 * sw + bb.w, 0.f);
        } else { acc[0] = acc[1] = acc[2] = acc[3] = 0.f; }
        if (v1 < n) {
            float di = dinv[v1]; float sw = di * di;
            float f0, f1, f2, f3;
            load4h(xw + (size_t)v1 * 128 + loff, f0, f1, f2, f3);
            acc[4] = fmaxf(acc[4] + f0 * sw + bb.x, 0.f);
            acc[5] = fmaxf(acc[5] + f1 * sw + bb.y, 0.f);
            acc[6] = fmaxf(acc[6] + f2 * sw + bb.z, 0.f);
            acc[7] = fmaxf(acc[7] + f3 * sw + bb.w, 0.f);
        } else { acc[4] = acc[5] = acc[6] = acc[7] = 0.f; }
        *reinterpret_cast<half2*>(&As[lr0][lane * 4])     = __floats2half2_rn(acc[0], acc[1]);
        *reinterpret_cast<half2*>(&As[lr0][lane * 4 + 2]) = __floats2half2_rn(acc[2], acc[3]);
        *reinterpret_cast<half2*>(&As[lr1][lane * 4])     = __floats2half2_rn(acc[4], acc[5]);
        *reinterpret_cast<half2*>(&As[lr1][lane * 4 + 2]) = __floats2half2_rn(acc[6], acc[7]);
    }
    __syncthreads();

    // phase 2: 16 warps, warp tile 32x32 (wm: M group, wn: N group)
    int wm = warpId & 3;
    int wn = warpId >> 2;              // 0..3
    wmma::fragment<wmma::accumulator, 16, 16, 16, float> acc2[2][2];
    #pragma unroll
    for (int i = 0; i < 2; i++)
        #pragma unroll
        for (int j = 0; j < 2; j++) wmma::fill_fragment(acc2[i][j], 0.0f);

    for (int kt2 = 0; kt2 < 128; kt2 += 32) {
        #pragma unroll
        for (int p = 0; p < 2; p++) {
            int idx = tid + p * 512;
            int r = idx >> 5;
            int c4 = (idx & 31) * 4;
            float4 v = *reinterpret_cast<const float4*>(W2 + (size_t)(kt2 + r) * 128 + c4);
            *reinterpret_cast<half2*>(&Ws[r][c4])     = __floats2half2_rn(v.x, v.y);
            *reinterpret_cast<half2*>(&Ws[r][c4 + 2]) = __floats2half2_rn(v.z, v.w);
        }
        __syncthreads();
        #pragma unroll
        for (int kk = 0; kk < 2; kk++) {
            int k0 = kt2 + kk * 16;
            wmma::fragment<wmma::matrix_a, 16, 16, 16, __half, wmma::row_major> af[2];
            wmma::fragment<wmma::matrix_b, 16, 16, 16, __half, wmma::row_major> bf[2];
            #pragma unroll
            for (int i = 0; i < 2; i++)
                wmma::load_matrix_sync(af[i], &As[wm * 32 + i * 16][k0], AS_STRIDE);
            #pragma unroll
            for (int j = 0; j < 2; j++)
                wmma::load_matrix_sync(bf[j], &Ws[kk * 16][wn * 32 + j * 16], AS_STRIDE);
            #pragma unroll
            for (int i = 0; i < 2; i++)
                #pragma unroll
                for (int j = 0; j < 2; j++)
                    wmma::mma_sync(acc2[i][j], af[i], bf[j], acc2[i][j]);
        }
        __syncthreads();
    }
    // epilogue: two N-half passes through ebuf (128x64 fp32)
    int er = tid >> 2;
    int ec0 = (tid & 3) * 16;
    #pragma unroll
    for (int p = 0; p < 2; p++) {
        if ((wn >> 1) == p) {
            int colbase = (wn & 1) * 32;
            #pragma unroll
            for (int i = 0; i < 2; i++)
                #pragma unroll
                for (int j = 0; j < 2; j++)
                    wmma::store_matrix_sync(&ebuf[(wm * 32 + i * 16) * 64 + colbase + j * 16],
                                            acc2[i][j], 64, wmma::mem_row_major);
        }
        __syncthreads();
        const float* src = ebuf + er * 64 + ec0;
        __half* dst = C + (size_t)(row0 + er) * 128 + p * 64 + ec0;
        #pragma unroll
        for (int k = 0; k < 16; k += 2)
            *reinterpret_cast<half2*>(dst + k) = __floats2half2_rn(src[k], src[k + 1]);
        __syncthreads();
    }
}

// ---------------- layer-2 aggregation: warp per TWO dst nodes ----------------
__global__ __launch_bounds__(256)
void agg_warp2_kernel(const __half* __restrict__ xw, __half* __restrict__ out,
                      const float* __restrict__ bias,
                      const int* __restrict__ rowptr, const int2* __restrict__ epair,
                      const float* __restrict__ dinv, int n) {
    int w = (blockIdx.x * blockDim.x + threadIdx.x) >> 5;
    int lane = threadIdx.x & 31;
    int v0 = 2 * w;
    int v1 = 2 * w + 1;
    if (v0 >= n) return;
    size_t loff = (size_t)lane * 4;
    float acc[8] = {0.f, 0.f, 0.f, 0.f, 0.f, 0.f, 0.f, 0.f};
    int e0 = rowptr[v0], end0 = rowptr[v0 + 1];
    int e1 = 0, end1 = 0;
    if (v1 < n) { e1 = rowptr[v1]; end1 = rowptr[v1 + 1]; }
    agg_pair(xw, loff, epair, e0, end0, e1, end1, acc);
    float4 bbv = *reinterpret_cast<const float4*>(bias + loff);
    {
        float di = dinv[v0]; float sw = di * di;
        float f0, f1, f2, f3;
        load4h(xw + (size_t)v0 * 128 + loff, f0, f1, f2, f3);
        store4h(out + (size_t)v0 * 128 + loff,
                fmaxf(acc[0] + f0 * sw + bbv.x, 0.f), fmaxf(acc[1] + f1 * sw + bbv.y, 0.f),
                fmaxf(acc[2] + f2 * sw + bbv.z, 0.f), fmaxf(acc[3] + f3 * sw + bbv.w, 0.f));
    }
    if (v1 < n) {
        float di = dinv[v1]; float sw = di * di;
        float f0, f1, f2, f3;
        load4h(xw + (size_t)v1 * 128 + loff, f0, f1, f2, f3);
        store4h(out + (size_t)v1 * 128 + loff,
                fmaxf(acc[4] + f0 * sw + bbv.x, 0.f), fmaxf(acc[5] + f1 * sw + bbv.y, 0.f),
                fmaxf(acc[6] + f2 * sw + bbv.z, 0.f), fmaxf(acc[7] + f3 * sw + bbv.w, 0.f));
    }
}

// ---------------- mean-pool: warp per segment ----------------
__global__ void pool_warp_kernel(const __half* __restrict__ h, __half* __restrict__ z,
                                 const int* __restrict__ prow, const int* __restrict__ pnode,
                                 int n) {
    int w = (blockIdx.x * blockDim.x + threadIdx.x) >> 5;
    int lane = threadIdx.x & 31;
    if (w >= n) return;
    int beg = prow[w];
    int end = prow[w + 1];
    size_t loff = (size_t)lane * 4;
    float a0 = 0.f, a1 = 0.f, a2 = 0.f, a3 = 0.f;
    #pragma unroll 4
    for (int m = beg; m < end; m++) {
        int nd = __ldg(pnode + m);
        float f0, f1, f2, f3;
        load4h(h + (size_t)nd * 128 + loff, f0, f1, f2, f3);
        a0 += f0; a1 += f1; a2 += f2; a3 += f3;
    }
    float inv = 1.0f / fmaxf((float)(end - beg), 1.0f);
    store4h(z + (size_t)w * 128 + loff, a0 * inv, a1 * inv, a2 * inv, a3 * inv);
}

// ---------------- decode: warp per edge ----------------
__global__ void decode_kernel(const __half* __restrict__ z,
                              const void* __restrict__ pos,
                              const void* __restrict__ neg,
                              const int* __restrict__ flag,
                              float* __restrict__ out, int ep) {
    int is64 = flag[0];
    int gw = (blockIdx.x * blockDim.x + threadIdx.x) >> 5;
    int lane = threadIdx.x & 31;
    int total = 2 * ep;
    if (gw >= total) return;
    int a, b;
    if (gw < ep) { a = idx_at(pos, gw, is64); b = idx_at(pos, (long long)ep + gw, is64); }
    else { int e = gw - ep; a = idx_at(neg, e, is64); b = idx_at(neg, (long long)ep + e, is64); }
    size_t loff = (size_t)lane * 4;
    float a0, a1, a2, a3, b0, b1, b2, b3;
    load4h(z + (size_t)a * 128 + loff, a0, a1, a2, a3);
    load4h(z + (size_t)b * 128 + loff, b0, b1, b2, b3);
    float s = a0 * b0 + a1 * b1 + a2 * b2 + a3 * b3;
    s += __shfl_xor_sync(0xffffffffu, s, 16);
    s += __shfl_xor_sync(0xffffffffu, s, 8);
    s += __shfl_xor_sync(0xffffffffu, s, 4);
    s += __shfl_xor_sync(0xffffffffu, s, 2);
    s += __shfl_xor_sync(0xffffffffu, s, 1);
    if (lane == 0) out[gw] = s;
}

// ---------------- launch ----------------
extern "C" void kernel_launch(void* const* d_in, const int* in_sizes, int n_in,
                              void* d_out, int out_size) {
    const float* x  = (const float*)d_in[0];
    const float* W1 = (const float*)d_in[1];
    const float* b1 = (const float*)d_in[2];
    const float* W2 = (const float*)d_in[3];
    const float* b2 = (const float*)d_in[4];
    const void*  edge = d_in[5];
    const void*  dict = d_in[6];
    const void*  pos  = d_in[7];
    const void*  neg  = d_in[8];
    float* out = (float*)d_out;

    const int n  = in_sizes[0] / HH;
    const int ne = in_sizes[5] / 2;
    const int ep = in_sizes[7] / 2;

    __half *xw, *h1, *h2, *z;
    float *dinv;
    int2* epair;
    int *cnt, *fill, *rowptr, *sflag, *pcnt, *pfill, *prow, *pnode, *flag;
    cudaGetSymbolAddress((void**)&xw,    g_xw);
    cudaGetSymbolAddress((void**)&h1,    g_h1);
    cudaGetSymbolAddress((void**)&h2,    g_h2);
    cudaGetSymbolAddress((void**)&z,     g_z);
    cudaGetSymbolAddress((void**)&dinv,  g_dinv);
    cudaGetSymbolAddress((void**)&epair, g_epair);
    cudaGetSymbolAddress((void**)&cnt,   g_cnt);
    cudaGetSymbolAddress((void**)&fill,  g_fill);
    cudaGetSymbolAddress((void**)&rowptr,g_rowptr);
    cudaGetSymbolAddress((void**)&sflag, g_sflag);
    cudaGetSymbolAddress((void**)&pcnt,  g_pcnt);
    cudaGetSymbolAddress((void**)&pfill, g_pfill);
    cudaGetSymbolAddress((void**)&prow,  g_prow);
    cudaGetSymbolAddress((void**)&pnode, g_pnode);
    cudaGetSymbolAddress((void**)&flag,  g_is64);

    const int nb1024 = (n + 1023) / 1024;           // 98 (must be <= 128)
    const int nbE = (ne + 255) / 256;
    const int nbN = (n + 255) / 256;
    const int gemm_blocks = (n + 127) / 128;
    const int aggw2_blocks = ((n + 1) / 2 + 7) / 8;
    const int poolw_blocks = (n + 7) / 8;

    // fork: GEMM1 depends only on x, W1
    cudaEventRecord(g_evA, 0);
    cudaStreamWaitEvent(g_s1, g_evA, 0);
    gemm16_kernel<<<gemm_blocks, 256, 0, g_s1>>>(x, W1, xw, n);
    cudaEventRecord(g_evB, g_s1);

    // preprocessing chain (default stream)
    zero_detect_kernel<<<nbN + 1, 256>>>(cnt, fill, pcnt, pfill, n, edge, flag, sflag);
    hist_dual_kernel<<<nbE + nbN, 256>>>(edge, (long long)ne, dict, n, flag, cnt, pcnt, nbE);
    {
        dim3 g1(nb1024, 2);
        scan_onepass_kernel<<<g1, 1024>>>(cnt, pcnt, rowptr, prow, dinv, sflag, n, nb1024);
    }
    scatter_dual_kernel<<<nbE + nbN, 256>>>(edge, (long long)ne, dict, n, flag,
                                            rowptr, fill, epair, dinv,
                                            prow, pfill, pnode, nbE);

    // join: fused agg1 + GEMM2 (512 threads)
    cudaStreamWaitEvent(0, g_evB, 0);
    agg_gemm_fused_kernel<<<gemm_blocks, 512>>>(xw, b1, W2, h1, rowptr, epair, dinv, n);
    // layer-2 aggregation
    agg_warp2_kernel<<<aggw2_blocks, 256>>>(h1, h2, b2, rowptr, epair, dinv, n);
    // mean pool
    pool_warp_kernel<<<poolw_blocks, 256>>>(h2, z, prow, pnode, n);
    // decode
    int total_warps = 2 * ep;
    int dec_blocks = (total_warps * 32 + 255) / 256;
    decode_kernel<<<dec_blocks, 256>>>(z, pos, neg, flag, out, ep);
}